// round 10
// baseline (speedup 1.0000x reference)
#include <cuda_runtime.h>
#include <cuda_fp16.h>

typedef unsigned int u32;
typedef unsigned long long ull;

#define GDIM 620
#define HH   150
#define HP   160
#define TP   64       // pairs per block (M tile)
#define NCHK 20       // 640/32
#define NT   256      // 8 warps: 2 m-blocks x 4 n-blocks

#define MMAX 1024
#define PMAX 50176

#define XH   40       // Gi/Gj/Ws row stride in halfs (LDSM conflict-free)
#define CST  168      // Ci row stride in floats

__device__ float  d_Apad[MMAX * HP];
__device__ float  d_Bpad[MMAX * HP];
__device__ float  d_distT[9 * HP];     // includes b1
__device__ float  d_genT[8 * HP];
__device__ float  d_spkT[3 * HP];
__device__ __half d_WtH[HP * 640];     // W1c^T fp16, [h][k], zero padded
__device__ __half d_g16[MMAX * 640];   // g fp16, row stride 640, zero padded
__device__ float  d_scores[PMAX];
__device__ int    d_starts[MMAX + 2];

// ---- f32x2 helpers for ab_k ----
union U2 { ull u; float f[2]; };
__device__ __forceinline__ ull pack2(float x, float y) { U2 v; v.f[0]=x; v.f[1]=y; return v.u; }
__device__ __forceinline__ void unpack2(ull v, float& x, float& y) { U2 t; t.u=v; x=t.f[0]; y=t.f[1]; }
__device__ __forceinline__ void fma2(ull& d, ull a, ull b) {
#if defined(__CUDA_ARCH__) && (__CUDA_ARCH__ >= 1000)
    asm("fma.rn.f32x2 %0, %1, %2, %3;" : "=l"(d) : "l"(a), "l"(b), "l"(d));
#else
    U2 dd,aa,bb; dd.u=d; aa.u=a; bb.u=b;
    dd.f[0]=fmaf(aa.f[0],bb.f[0],dd.f[0]); dd.f[1]=fmaf(aa.f[1],bb.f[1],dd.f[1]); d=dd.u;
#endif
}

__device__ __forceinline__ u32 s2u(const void* p) {
    u32 a;
    asm("{ .reg .u64 t; cvta.to.shared.u64 t, %1; cvt.u32.u64 %0, t; }" : "=r"(a) : "l"(p));
    return a;
}
__device__ __forceinline__ u32 hmul2u(u32 a, u32 b) {
    __half2 r = __hmul2(*(__half2*)&a, *(__half2*)&b);
    return *(u32*)&r;
}

#define MMA_F16(C, A, B0, B1)                                               \
    asm volatile("mma.sync.aligned.m16n8k16.row.col.f32.f16.f16.f32 "       \
        "{%0,%1,%2,%3}, {%4,%5,%6,%7}, {%8,%9}, {%0,%1,%2,%3};"             \
        : "+f"((C)[0]), "+f"((C)[1]), "+f"((C)[2]), "+f"((C)[3])            \
        : "r"((A)[0]), "r"((A)[1]), "r"((A)[2]), "r"((A)[3]),               \
          "r"(B0), "r"(B1))

#define LDSM4(R0, R1, R2, R3, ADDR)                                         \
    asm volatile("ldmatrix.sync.aligned.m8n8.x4.shared.b16 {%0,%1,%2,%3}, [%4];" \
        : "=r"(R0), "=r"(R1), "=r"(R2), "=r"(R3) : "r"(ADDR))
#define LDSM2(R0, R1, ADDR)                                                 \
    asm volatile("ldmatrix.sync.aligned.m8n8.x2.shared.b16 {%0,%1}, [%2];"  \
        : "=r"(R0), "=r"(R1) : "r"(ADDR))

#define CP16(DST, SRC)                                                      \
    asm volatile("cp.async.ca.shared.global [%0], [%1], 16;" :: "r"(DST), "l"(SRC) : "memory")
#define CP_COMMIT() asm volatile("cp.async.commit_group;" ::: "memory")
#define CP_WAIT1()  asm volatile("cp.async.wait_group 1;"  ::: "memory")

// ---- shared layout (bytes). 3-stage ring; Ci aliases upper part of ring.
#define SM_SI   0
#define SM_SJ   256
#define SM_DB   512
#define SM_GN   768
#define SM_SP   1024
#define SM_W2   1280
#define SM_SRED 1920                   // 64*4 floats
#define SM_BIG  2944
#define BUFSZ   23040                  // Gi 5120 + Gj 5120 + W 12800
#define GIOFF   0
#define GJOFF   5120
#define WOFF    10240
#define CIOFF   (SM_BIG + 26112)       // Ci: 64*168*4 = 43008 (ends at BIG+69120)
#define SM_TOT  (SM_BIG + 3 * BUFSZ)   // 72064 -> 3 CTAs/SM

// ---------------------------------------------------------------------------
// prep_k: b0 tables, b1 starts, [2,402) WtH fp16, [402,402+nG16) g fp16,
// rest output fill
// ---------------------------------------------------------------------------
__global__ void prep_k(float* __restrict__ out, int n,
                       const float* __restrict__ de, const float* __restrict__ ge,
                       const float* __restrict__ se, const float* __restrict__ W1,
                       const float* __restrict__ b1, const float* __restrict__ g,
                       const int* __restrict__ mids, int P, int M, int nG16) {
    int b = blockIdx.x;
    if (b == 0) {
        for (int e = threadIdx.x; e < 20 * HP; e += blockDim.x) {
            int row = e / HP, h = e % HP;
            const float* emb; int dbase; float* dst; float acc;
            if (row < 9)       { emb = de + row * 20;        dbase = 3 * GDIM;      dst = d_distT + row * HP + h;        acc = (h < HH) ? b1[h] : 0.0f; }
            else if (row < 17) { emb = ge + (row - 9) * 20;  dbase = 3 * GDIM + 20; dst = d_genT  + (row - 9) * HP + h;  acc = 0.0f; }
            else               { emb = se + (row - 17) * 20; dbase = 3 * GDIM + 40; dst = d_spkT  + (row - 17) * HP + h; acc = 0.0f; }
            if (h < HH) {
                #pragma unroll
                for (int k = 0; k < 20; k++) acc += emb[k] * W1[(dbase + k) * HH + h];
            }
            *dst = acc;
        }
    } else if (b == 1) {
        for (int m = threadIdx.x; m <= M; m += blockDim.x) {
            int lo = 0, hi = P;
            while (lo < hi) {
                int mid = (lo + hi) >> 1;
                if (mids[mid] < m) lo = mid + 1; else hi = mid;
            }
            d_starts[m] = lo;
        }
    } else if (b < 402) {
        int idx = (b - 2) * 256 + threadIdx.x;
        if (idx < HP * 640) {
            int h = idx / 640, k = idx % 640;
            const float* W1c = W1 + 2 * GDIM * HH;
            float v = (h < HH && k < GDIM) ? W1c[k * HH + h] : 0.0f;
            d_WtH[idx] = __float2half(v);
        }
    } else if (b < 402 + nG16) {
        int idx = (b - 402) * 256 + threadIdx.x;
        if (idx < M * 640) {
            int m = idx / 640, k = idx % 640;
            float v = (k < GDIM) ? g[m * GDIM + k] : 0.0f;
            d_g16[idx] = __float2half(v);
        }
    } else {
        int i = (b - 402 - nG16) * blockDim.x + threadIdx.x;
        if (i < n) out[i] = (i == 0) ? 1.0f : 1000.0f;
    }
}

// ---------------------------------------------------------------------------
// ab_k: A = g@W1a (y=0), B = g@W1b (y=1). 8 mentions/block, f32x2 accs.
// ---------------------------------------------------------------------------
#define ABT 160
__global__ __launch_bounds__(ABT) void ab_k(const float* __restrict__ g,
                                            const float* __restrict__ W1, int M) {
    __shared__ float gs[GDIM][10];
    const int m0 = blockIdx.x * 8;
    const int which = blockIdx.y;
    const int tid = threadIdx.x;

    for (int e = tid; e < 8 * GDIM; e += ABT) {
        int mm = e / GDIM, d = e % GDIM;
        int m = m0 + mm;
        gs[d][mm] = (m < M) ? g[m * GDIM + d] : 0.0f;
    }
    __syncthreads();

    const int h = tid;
    ull acc[4] = {0ull, 0ull, 0ull, 0ull};
    if (h < HH) {
        const float* w = W1 + (which ? GDIM * HH : 0) + h;
        #pragma unroll 4
        for (int d = 0; d < GDIM; d++) {
            float wv = __ldg(&w[d * HH]);
            ull wp = pack2(wv, wv);
            const ull* grow = (const ull*)&gs[d][0];
            fma2(acc[0], grow[0], wp);
            fma2(acc[1], grow[1], wp);
            fma2(acc[2], grow[2], wp);
            fma2(acc[3], grow[3], wp);
        }
    }
    float* dst = which ? d_Bpad : d_Apad;
    #pragma unroll
    for (int r = 0; r < 4; r++) {
        float x, y; unpack2(acc[r], x, y);
        int m = m0 + 2 * r;
        if (m < M)     dst[m * HP + h] = x;
        if (m + 1 < M) dst[(m + 1) * HP + h] = y;
    }
}

// ---------------------------------------------------------------------------
// pair_k: 64 pairs x 160 h, 8 warps = 2m x 4n. Exact fp32 C init; fp16 mma.
// Raw Gi/Gj/W chunks via cp.async 3-stage ring; A = hmul2(ldsm(Gi), ldsm(Gj))
// in registers (no product round trip). 3 CTAs/SM.
// ---------------------------------------------------------------------------
__global__ __launch_bounds__(NT, 3) void pair_k(
    const float* __restrict__ W2,  const float* __restrict__ b2,
    const float* __restrict__ ms,
    const int* __restrict__ mids,  const int* __restrict__ aids,
    const int* __restrict__ dists, const int* __restrict__ gens,
    const int* __restrict__ spks,  int P)
{
    extern __shared__ char smc[];
    int*   s_si = (int*)(smc + SM_SI);
    int*   s_sj = (int*)(smc + SM_SJ);
    int*   s_db = (int*)(smc + SM_DB);
    int*   s_gn = (int*)(smc + SM_GN);
    int*   s_sp = (int*)(smc + SM_SP);
    float* w2s  = (float*)(smc + SM_W2);
    float* sred = (float*)(smc + SM_SRED);
    float* Ci   = (float*)(smc + CIOFF);

    const u32 smu = s2u(smc);
    const int tid = threadIdx.x;
    const int pb  = blockIdx.x * TP;

    if (tid < TP) {
        int p = pb + tid;
        bool ok = p < P;
        s_si[tid] = ok ? mids[p] : 0;
        s_sj[tid] = ok ? aids[p] : 0;
        int dd = ok ? dists[p] : 0;
        s_db[tid] = (dd >= 1) + (dd >= 2) + (dd >= 3) + (dd >= 4) +
                    (dd >= 8) + (dd >= 16) + (dd >= 32) + (dd >= 64);
        s_gn[tid] = ok ? gens[p] : 0;
        s_sp[tid] = ok ? spks[p] : 0;
    }
    if (tid < HP) w2s[tid] = (tid < HH) ? W2[tid] : 0.0f;
    __syncthreads();

    // fill assignment: 4 threads per pair row
    const int myrow = tid >> 2, q = tid & 3;
    const char* gi_src = (const char*)(d_g16 + s_si[myrow] * 640) + q * 16;
    const char* gj_src = (const char*)(d_g16 + s_sj[myrow] * 640) + q * 16;
    const char* w_src  = (const char*)d_WtH + tid * 1280;   // valid if tid<160
    const u32 gi_dst = smu + SM_BIG + GIOFF + (myrow * XH + q * 8) * 2;
    const u32 gj_dst = smu + SM_BIG + GJOFF + (myrow * XH + q * 8) * 2;
    const u32 w_dst  = smu + SM_BIG + WOFF + tid * (XH * 2);

    // ---- stage exact init tile Ci[64][160] (fp32)
    {
        const float4* A4 = (const float4*)d_Apad;
        const float4* B4 = (const float4*)d_Bpad;
        const float4* D4 = (const float4*)d_distT;
        const float4* G4 = (const float4*)d_genT;
        const float4* S4 = (const float4*)d_spkT;
        #pragma unroll
        for (int it = 0; it < (TP * 40) / NT; it++) {
            int e = tid + NT * it;
            int row = e / 40, c4 = e % 40;
            float4 a = __ldg(&A4[s_si[row] * 40 + c4]);
            float4 b = __ldg(&B4[s_sj[row] * 40 + c4]);
            float4 d = __ldg(&D4[s_db[row] * 40 + c4]);
            float4 gg = __ldg(&G4[s_gn[row] * 40 + c4]);
            float4 s = __ldg(&S4[s_sp[row] * 40 + c4]);
            float4 v = make_float4(a.x+b.x+d.x+gg.x+s.x, a.y+b.y+d.y+gg.y+s.y,
                                   a.z+b.z+d.z+gg.z+s.z, a.w+b.w+d.w+gg.w+s.w);
            *(float4*)(Ci + row * CST + c4 * 4) = v;
        }
    }
    __syncthreads();

    // ---- chunk 0 fills (buf0 disjoint from Ci region) overlap frag reads
    {
        CP16(gi_dst, gi_src); CP16(gj_dst, gj_src);
        if (tid < HP) {
            CP16(w_dst, w_src); CP16(w_dst + 16, w_src + 16);
            CP16(w_dst + 32, w_src + 32); CP16(w_dst + 48, w_src + 48);
        }
        CP_COMMIT();
    }

    const int lid = tid & 31, wi = tid >> 5;
    const int mBlk = (wi & 1) * 32, nBlk = (wi >> 1) * 40;
    const int tig = lid & 3, grp = lid >> 2;

    // ---- load C fragments from Ci
    float c[2][5][4];
    #pragma unroll
    for (int ma = 0; ma < 2; ma++) {
        int r = mBlk + ma * 16 + grp;
        #pragma unroll
        for (int na = 0; na < 5; na++) {
            int col = nBlk + na * 8 + 2 * tig;
            float2 lo = *(const float2*)(Ci + r * CST + col);
            float2 hi = *(const float2*)(Ci + (r + 8) * CST + col);
            c[ma][na][0] = lo.x; c[ma][na][1] = lo.y;
            c[ma][na][2] = hi.x; c[ma][na][3] = hi.y;
        }
    }
    __syncthreads();    // frag reads done -> bufs 1,2 region reusable

    // ---- chunk 1 fills
    {
        CP16(gi_dst + BUFSZ, gi_src + 64); CP16(gj_dst + BUFSZ, gj_src + 64);
        if (tid < HP) {
            const char* src = w_src + 64;
            u32 dst = w_dst + BUFSZ;
            CP16(dst, src); CP16(dst + 16, src + 16);
            CP16(dst + 32, src + 32); CP16(dst + 48, src + 48);
        }
        CP_COMMIT();
    }

    // ldmatrix lane address components
    const int aRow = ((lid >> 3) & 1) * 8 + (lid & 7);
    const int aK   = (lid >> 4) * 8;
    const int bRow = (lid >> 4) * 8 + (lid & 7);
    const int bK   = ((lid >> 3) & 1) * 8;
    const int b2r  = nBlk + 32 + (lid & 7);
    const int b2k  = ((lid >> 3) & 1) * 8;

    int buf = 0;
    for (int cch = 0; cch < NCHK; cch++) {
        CP_WAIT1();          // chunk cch landed (chunk cch+1 may be in flight)
        __syncthreads();     // all threads' copies visible; ring slot freed

        // issue chunk cch+2 into buf (cch+2)%3  (post-barrier: race-free)
        if (cch + 2 < NCHK) {
            int nb = buf + 2; if (nb >= 3) nb -= 3;
            u32 off = nb * BUFSZ;
            const char* gsi = gi_src + (cch + 2) * 64;
            const char* gsj = gj_src + (cch + 2) * 64;
            CP16(gi_dst + off, gsi); CP16(gj_dst + off, gsj);
            if (tid < HP) {
                const char* src = w_src + (cch + 2) * 64;
                u32 dst = w_dst + off;
                CP16(dst, src); CP16(dst + 16, src + 16);
                CP16(dst + 32, src + 32); CP16(dst + 48, src + 48);
            }
        }
        CP_COMMIT();         // commit every iter (empty ok) for uniform counts

        // ---- mma on chunk cch: A = hmul2(Gi, Gj) fragments
        const u32 base = smu + SM_BIG + buf * BUFSZ;
        #pragma unroll
        for (int s = 0; s < 2; s++) {
            u32 a[2][4];
            #pragma unroll
            for (int ma = 0; ma < 2; ma++) {
                u32 roff = ((mBlk + ma * 16 + aRow) * XH + s * 16 + aK) * 2;
                u32 ai0, ai1, ai2, ai3, aj0, aj1, aj2, aj3;
                LDSM4(ai0, ai1, ai2, ai3, base + GIOFF + roff);
                LDSM4(aj0, aj1, aj2, aj3, base + GJOFF + roff);
                a[ma][0] = hmul2u(ai0, aj0); a[ma][1] = hmul2u(ai1, aj1);
                a[ma][2] = hmul2u(ai2, aj2); a[ma][3] = hmul2u(ai3, aj3);
            }
            #pragma unroll
            for (int ng = 0; ng < 2; ng++) {
                u32 ad = base + WOFF + (((nBlk + ng * 16 + bRow) * XH + s * 16 + bK) * 2);
                u32 b0, b1, b2v, b3;
                LDSM4(b0, b1, b2v, b3, ad);
                MMA_F16(c[0][2*ng],     a[0], b0, b1);
                MMA_F16(c[1][2*ng],     a[1], b0, b1);
                MMA_F16(c[0][2*ng + 1], a[0], b2v, b3);
                MMA_F16(c[1][2*ng + 1], a[1], b2v, b3);
            }
            {   // last 8 cols
                u32 ad = base + WOFF + ((b2r * XH + s * 16 + b2k) * 2);
                u32 b0, b1;
                LDSM2(b0, b1, ad);
                MMA_F16(c[0][4], a[0], b0, b1);
                MMA_F16(c[1][4], a[1], b0, b1);
            }
        }
        if (++buf == 3) buf = 0;
    }

    // ---- epilogue: relu + dot W2, reduce over tig, combine 4 n-blocks
    float part[2][2] = {{0.f, 0.f}, {0.f, 0.f}};
    #pragma unroll
    for (int ma = 0; ma < 2; ma++)
        #pragma unroll
        for (int na = 0; na < 5; na++) {
            int col = nBlk + na * 8 + 2 * tig;
            float w0 = w2s[col], w1 = w2s[col + 1];
            float v0 = fmaxf(c[ma][na][0], 0.f), v1 = fmaxf(c[ma][na][1], 0.f);
            float v2 = fmaxf(c[ma][na][2], 0.f), v3 = fmaxf(c[ma][na][3], 0.f);
            part[ma][0] += v0 * w0 + v1 * w1;
            part[ma][1] += v2 * w0 + v3 * w1;
        }
    #pragma unroll
    for (int ma = 0; ma < 2; ma++)
        #pragma unroll
        for (int rr = 0; rr < 2; rr++) {
            float v = part[ma][rr];
            v += __shfl_xor_sync(0xffffffffu, v, 1);
            v += __shfl_xor_sync(0xffffffffu, v, 2);
            part[ma][rr] = v;
        }
    if (tig == 0) {
        int nb = wi >> 1;
        #pragma unroll
        for (int ma = 0; ma < 2; ma++)
            #pragma unroll
            for (int rr = 0; rr < 2; rr++) {
                int row = mBlk + ma * 16 + grp + 8 * rr;
                sred[row * 4 + nb] = part[ma][rr];
            }
    }
    __syncthreads();
    if (tid < TP) {
        int p = pb + tid;
        if (p < P) {
            float s = sred[tid * 4] + sred[tid * 4 + 1] +
                      sred[tid * 4 + 2] + sred[tid * 4 + 3];
            d_scores[p] = s + __ldg(b2) + ms[s_si[tid]] + ms[s_sj[tid]];
        }
    }
}

// ---------------------------------------------------------------------------
// Ragged softmax (+epsilon logit 0), one warp per mention
// ---------------------------------------------------------------------------
__global__ void softmax_k(float* __restrict__ out, int M) {
    int warp = (blockIdx.x * blockDim.x + threadIdx.x) >> 5;
    int lane = threadIdx.x & 31;
    if (warp >= M) return;
    int s0 = d_starts[warp], s1 = d_starts[warp + 1];
    int n = s1 - s0;

    float mx = 0.0f;
    for (int i = lane; i < n; i += 32) mx = fmaxf(mx, d_scores[s0 + i]);
    #pragma unroll
    for (int off = 16; off; off >>= 1) mx = fmaxf(mx, __shfl_xor_sync(0xffffffffu, mx, off));

    float sum = 0.0f;
    for (int i = lane; i < n; i += 32) sum += expf(d_scores[s0 + i] - mx);
    #pragma unroll
    for (int off = 16; off; off >>= 1) sum += __shfl_xor_sync(0xffffffffu, sum, off);

    float eps = expf(-mx);
    float inv = 1.0f / (sum + eps);
    float* row = out + (warp + 1) * 161;
    for (int i = lane; i < n; i += 32) row[i] = expf(d_scores[s0 + i] - mx) * inv;
    if (lane == 0) row[n] = eps * inv;
}

// ---------------------------------------------------------------------------
extern "C" void kernel_launch(void* const* d_in, const int* in_sizes, int n_in,
                              void* d_out, int out_size) {
    const float* g_i   = (const float*)d_in[0];
    const float* msc   = (const float*)d_in[1];
    const float* de    = (const float*)d_in[2];
    const float* ge    = (const float*)d_in[3];
    const float* se    = (const float*)d_in[4];
    const float* W1    = (const float*)d_in[5];
    const float* b1    = (const float*)d_in[6];
    const float* W2    = (const float*)d_in[7];
    const float* b2    = (const float*)d_in[8];
    const int*   mids  = (const int*)d_in[9];
    const int*   aids  = (const int*)d_in[10];
    const int*   dists = (const int*)d_in[11];
    const int*   gens  = (const int*)d_in[12];
    const int*   spks  = (const int*)d_in[13];

    int M = in_sizes[1];
    int P = in_sizes[9];
    float* out = (float*)d_out;

    int nG16  = (M * 640 + 255) / 256;
    int fillB = (out_size + 255) / 256;

    cudaFuncSetAttribute(pair_k, cudaFuncAttributeMaxDynamicSharedMemorySize, SM_TOT);

    prep_k<<<402 + nG16 + fillB, 256>>>(out, out_size, de, ge, se, W1, b1, g_i,
                                        mids, P, M, nG16);
    ab_k<<<dim3((M + 7) / 8, 2), ABT>>>(g_i, W1, M);
    pair_k<<<(P + TP - 1) / TP, NT, SM_TOT>>>(W2, b2, msc,
                                              mids, aids, dists, gens, spks, P);
    softmax_k<<<(M + 7) / 8, 256>>>(out, M);
}

// round 11
// speedup vs baseline: 1.0846x; 1.0846x over previous
#include <cuda_runtime.h>
#include <cuda_fp16.h>

typedef unsigned int u32;
typedef unsigned long long ull;

#define GDIM 620
#define HH   150
#define HP   160
#define TP   64       // pairs per block (M tile)
#define NCHK 20       // 640/32
#define NT   256      // 8 warps: 2 m-blocks x 4 n-blocks

#define MMAX 1024
#define PMAX 50176

#define XH   40       // Xs/Ws row stride in halfs (LDSM conflict-free)
#define CST  168      // Ci row stride in floats

__device__ float  d_Apad[MMAX * HP];
__device__ float  d_Bpad[MMAX * HP];
__device__ float  d_distT[9 * HP];     // includes b1
__device__ float  d_genT[8 * HP];
__device__ float  d_spkT[3 * HP];
__device__ __half d_WtH[HP * 640];     // W1c^T fp16, [h][k], zero padded
__device__ __half d_g16[MMAX * 640];   // g fp16, row stride 640, zero padded
__device__ float  d_scores[PMAX];
__device__ int    d_starts[MMAX + 2];

// ---- f32x2 helpers for ab blocks ----
union U2 { ull u; float f[2]; };
__device__ __forceinline__ ull pack2(float x, float y) { U2 v; v.f[0]=x; v.f[1]=y; return v.u; }
__device__ __forceinline__ void unpack2(ull v, float& x, float& y) { U2 t; t.u=v; x=t.f[0]; y=t.f[1]; }
__device__ __forceinline__ void fma2(ull& d, ull a, ull b) {
#if defined(__CUDA_ARCH__) && (__CUDA_ARCH__ >= 1000)
    asm("fma.rn.f32x2 %0, %1, %2, %3;" : "=l"(d) : "l"(a), "l"(b), "l"(d));
#else
    U2 dd,aa,bb; dd.u=d; aa.u=a; bb.u=b;
    dd.f[0]=fmaf(aa.f[0],bb.f[0],dd.f[0]); dd.f[1]=fmaf(aa.f[1],bb.f[1],dd.f[1]); d=dd.u;
#endif
}

__device__ __forceinline__ u32 s2u(const void* p) {
    u32 a;
    asm("{ .reg .u64 t; cvta.to.shared.u64 t, %1; cvt.u32.u64 %0, t; }" : "=r"(a) : "l"(p));
    return a;
}

#define MMA_F16(C, A, B0, B1)                                               \
    asm volatile("mma.sync.aligned.m16n8k16.row.col.f32.f16.f16.f32 "       \
        "{%0,%1,%2,%3}, {%4,%5,%6,%7}, {%8,%9}, {%0,%1,%2,%3};"             \
        : "+f"((C)[0]), "+f"((C)[1]), "+f"((C)[2]), "+f"((C)[3])            \
        : "r"((A)[0]), "r"((A)[1]), "r"((A)[2]), "r"((A)[3]),               \
          "r"(B0), "r"(B1))

#define LDSM4(R0, R1, R2, R3, ADDR)                                         \
    asm volatile("ldmatrix.sync.aligned.m8n8.x4.shared.b16 {%0,%1,%2,%3}, [%4];" \
        : "=r"(R0), "=r"(R1), "=r"(R2), "=r"(R3) : "r"(ADDR))
#define LDSM2(R0, R1, ADDR)                                                 \
    asm volatile("ldmatrix.sync.aligned.m8n8.x2.shared.b16 {%0,%1}, [%2];"  \
        : "=r"(R0), "=r"(R1) : "r"(ADDR))

#define CP16(DST, SRC)                                                      \
    asm volatile("cp.async.ca.shared.global [%0], [%1], 16;" :: "r"(DST), "l"(SRC) : "memory")
#define CP_COMMIT() asm volatile("cp.async.commit_group;" ::: "memory")
#define CP_WAIT0()  asm volatile("cp.async.wait_group 0;"  ::: "memory")

// ---- shared layout (bytes). BIG: Ci (init) aliases Xs/Ws (mainloop)
#define SM_SI   0
#define SM_SJ   256
#define SM_DB   512
#define SM_GN   768
#define SM_SP   1024
#define SM_W2   1280
#define SM_SRED 1920                   // 64*4 floats
#define SM_BIG  2944
#define CI_BYTES (TP * CST * 4)        // 43008
#define XSOFF(b) (SM_BIG + (b) * 17920)   // Xs: 64*40*2 = 5120
#define WSOFF(b) (XSOFF(b) + 5120)        // Ws: 160*40*2 = 12800
#define SM_TOT  (SM_BIG + CI_BYTES)    // 45952 -> 3 CTAs/SM

// ---------------------------------------------------------------------------
// prep_k (fused): b0 tables, b1 starts, [2,402) WtH fp16, then g16 convert,
// then ab blocks (A=g@W1a / B=g@W1b, 8 mentions each), then output fill.
// All branches independent -> overlap across SMs in one launch.
// ---------------------------------------------------------------------------
__global__ void prep_k(float* __restrict__ out, int n,
                       const float* __restrict__ de, const float* __restrict__ ge,
                       const float* __restrict__ se, const float* __restrict__ W1,
                       const float* __restrict__ b1, const float* __restrict__ g,
                       const int* __restrict__ mids, int P, int M,
                       int nG16, int nAB) {
    __shared__ float gs[GDIM][10];     // used only by ab blocks
    int b = blockIdx.x;
    if (b == 0) {
        for (int e = threadIdx.x; e < 20 * HP; e += blockDim.x) {
            int row = e / HP, h = e % HP;
            const float* emb; int dbase; float* dst; float acc;
            if (row < 9)       { emb = de + row * 20;        dbase = 3 * GDIM;      dst = d_distT + row * HP + h;        acc = (h < HH) ? b1[h] : 0.0f; }
            else if (row < 17) { emb = ge + (row - 9) * 20;  dbase = 3 * GDIM + 20; dst = d_genT  + (row - 9) * HP + h;  acc = 0.0f; }
            else               { emb = se + (row - 17) * 20; dbase = 3 * GDIM + 40; dst = d_spkT  + (row - 17) * HP + h; acc = 0.0f; }
            if (h < HH) {
                #pragma unroll
                for (int k = 0; k < 20; k++) acc += emb[k] * W1[(dbase + k) * HH + h];
            }
            *dst = acc;
        }
    } else if (b == 1) {
        for (int m = threadIdx.x; m <= M; m += blockDim.x) {
            int lo = 0, hi = P;
            while (lo < hi) {
                int mid = (lo + hi) >> 1;
                if (mids[mid] < m) lo = mid + 1; else hi = mid;
            }
            d_starts[m] = lo;
        }
    } else if (b < 402) {
        int idx = (b - 2) * 256 + threadIdx.x;
        if (idx < HP * 640) {
            int h = idx / 640, k = idx % 640;
            const float* W1c = W1 + 2 * GDIM * HH;
            float v = (h < HH && k < GDIM) ? W1c[k * HH + h] : 0.0f;
            d_WtH[idx] = __float2half(v);
        }
    } else if (b < 402 + nG16) {
        int idx = (b - 402) * 256 + threadIdx.x;
        if (idx < M * 640) {
            int m = idx / 640, k = idx % 640;
            float v = (k < GDIM) ? g[m * GDIM + k] : 0.0f;
            d_g16[idx] = __float2half(v);
        }
    } else if (b < 402 + nG16 + nAB) {
        // ---- ab block: A = g@W1a (which=0) or B = g@W1b (which=1)
        int idx = b - 402 - nG16;
        int m0 = (idx >> 1) * 8;
        int which = idx & 1;
        int tid = threadIdx.x;

        for (int e = tid; e < 8 * GDIM; e += 256) {
            int mm = e / GDIM, d = e % GDIM;
            int m = m0 + mm;
            gs[d][mm] = (m < M) ? g[m * GDIM + d] : 0.0f;
        }
        __syncthreads();

        if (tid < HP) {
            const int h = tid;
            ull acc[4] = {0ull, 0ull, 0ull, 0ull};
            if (h < HH) {
                const float* w = W1 + (which ? GDIM * HH : 0) + h;
                #pragma unroll 4
                for (int d = 0; d < GDIM; d++) {
                    float wv = __ldg(&w[d * HH]);
                    ull wp = pack2(wv, wv);
                    const ull* grow = (const ull*)&gs[d][0];
                    fma2(acc[0], grow[0], wp);
                    fma2(acc[1], grow[1], wp);
                    fma2(acc[2], grow[2], wp);
                    fma2(acc[3], grow[3], wp);
                }
            }
            float* dst = which ? d_Bpad : d_Apad;
            #pragma unroll
            for (int r = 0; r < 4; r++) {
                float x, y; unpack2(acc[r], x, y);
                int m = m0 + 2 * r;
                if (m < M)     dst[m * HP + h] = x;
                if (m + 1 < M) dst[(m + 1) * HP + h] = y;
            }
        }
    } else {
        int i = (b - 402 - nG16 - nAB) * blockDim.x + threadIdx.x;
        if (i < n) out[i] = (i == 0) ? 1.0f : 1000.0f;
    }
}

// ---------------------------------------------------------------------------
// pair_k: 64 pairs x 160 h per CTA, 8 warps = 2 m-blocks(32) x 4 n-blocks(40).
// Exact fp32 C init; fp16 m16n8k16 Hadamard GEMM; fp16 g source. 3 CTAs/SM.
// (R9 mainloop: X product via register prefetch + STS, single LDSM4 per A frag)
// ---------------------------------------------------------------------------
__global__ __launch_bounds__(NT, 3) void pair_k(
    const float* __restrict__ W2,  const float* __restrict__ b2,
    const float* __restrict__ ms,
    const int* __restrict__ mids,  const int* __restrict__ aids,
    const int* __restrict__ dists, const int* __restrict__ gens,
    const int* __restrict__ spks,  int P)
{
    extern __shared__ char smc[];
    int*   s_si = (int*)(smc + SM_SI);
    int*   s_sj = (int*)(smc + SM_SJ);
    int*   s_db = (int*)(smc + SM_DB);
    int*   s_gn = (int*)(smc + SM_GN);
    int*   s_sp = (int*)(smc + SM_SP);
    float* w2s  = (float*)(smc + SM_W2);
    float* sred = (float*)(smc + SM_SRED);
    float* Ci   = (float*)(smc + SM_BIG);

    const u32 smu = s2u(smc);
    const int tid = threadIdx.x;
    const int pb  = blockIdx.x * TP;

    if (tid < TP) {
        int p = pb + tid;
        bool ok = p < P;
        s_si[tid] = ok ? mids[p] : 0;
        s_sj[tid] = ok ? aids[p] : 0;
        int dd = ok ? dists[p] : 0;
        s_db[tid] = (dd >= 1) + (dd >= 2) + (dd >= 3) + (dd >= 4) +
                    (dd >= 8) + (dd >= 16) + (dd >= 32) + (dd >= 64);
        s_gn[tid] = ok ? gens[p] : 0;
        s_sp[tid] = ok ? spks[p] : 0;
    }
    if (tid < HP) w2s[tid] = (tid < HH) ? W2[tid] : 0.0f;
    __syncthreads();

    // ---- stage exact init tile Ci[64][160] (fp32)
    {
        const float4* A4 = (const float4*)d_Apad;
        const float4* B4 = (const float4*)d_Bpad;
        const float4* D4 = (const float4*)d_distT;
        const float4* G4 = (const float4*)d_genT;
        const float4* S4 = (const float4*)d_spkT;
        #pragma unroll
        for (int it = 0; it < (TP * 40) / NT; it++) {
            int e = tid + NT * it;
            int row = e / 40, c4 = e % 40;
            float4 a = __ldg(&A4[s_si[row] * 40 + c4]);
            float4 b = __ldg(&B4[s_sj[row] * 40 + c4]);
            float4 d = __ldg(&D4[s_db[row] * 40 + c4]);
            float4 gg = __ldg(&G4[s_gn[row] * 40 + c4]);
            float4 s = __ldg(&S4[s_sp[row] * 40 + c4]);
            float4 v = make_float4(a.x+b.x+d.x+gg.x+s.x, a.y+b.y+d.y+gg.y+s.y,
                                   a.z+b.z+d.z+gg.z+s.z, a.w+b.w+d.w+gg.w+s.w);
            *(float4*)(Ci + row * CST + c4 * 4) = v;
        }
    }
    __syncthreads();

    const int lid = tid & 31, wi = tid >> 5;
    const int mBlk = (wi & 1) * 32, nBlk = (wi >> 1) * 40;
    const int tig = lid & 3, grp = lid >> 2;

    // ---- load C fragments from Ci (2 m-atoms x 5 n-atoms)
    float c[2][5][4];
    #pragma unroll
    for (int ma = 0; ma < 2; ma++) {
        int r = mBlk + ma * 16 + grp;
        #pragma unroll
        for (int na = 0; na < 5; na++) {
            int col = nBlk + na * 8 + 2 * tig;
            float2 lo = *(const float2*)(Ci + r * CST + col);
            float2 hi = *(const float2*)(Ci + (r + 8) * CST + col);
            c[ma][na][0] = lo.x; c[ma][na][1] = lo.y;
            c[ma][na][2] = hi.x; c[ma][na][3] = hi.y;
        }
    }

    // ---- pipeline setup
    const int myrow = tid >> 2, q = tid & 3;          // row 0..63, quarter 0..3
    const uint4* gi16 = (const uint4*)(d_g16 + s_si[myrow] * 640) + q;  // +q*8 halfs
    const uint4* gj16 = (const uint4*)(d_g16 + s_sj[myrow] * 640) + q;
    const char*  wsrc = (const char*)d_WtH + tid * 1280;   // row tid (if <160)

    // ldmatrix lane address components
    const int aRow = ((lid >> 3) & 1) * 8 + (lid & 7);
    const int aK   = (lid >> 4) * 8;
    const int bRow = (lid >> 4) * 8 + (lid & 7);
    const int bK   = ((lid >> 3) & 1) * 8;
    const int b2r  = nBlk + 32 + (lid & 7);           // LDSM2: last 8 cols
    const int b2k  = ((lid >> 3) & 1) * 8;

    uint4 xi, xj;
    xi = __ldg(gi16);   // chunk 0 (uint4 index stride 4 per chunk: 32 halfs)
    xj = __ldg(gj16);
    __syncthreads();   // Ci fragment reads done; BIG region reusable

    if (tid < HP) {    // W chunk 0
        u32 dst = smu + WSOFF(0) + tid * (XH * 2);
        CP16(dst, wsrc); CP16(dst + 16, wsrc + 16);
        CP16(dst + 32, wsrc + 32); CP16(dst + 48, wsrc + 48);
    }
    CP_COMMIT();

    for (int cch = 0; cch < NCHK; cch++) {
        const int buf = cch & 1;
        // store prefetched X chunk: 4 x hmul2 -> 16B
        {
            const __half2* a2 = (const __half2*)&xi;
            const __half2* b2h = (const __half2*)&xj;
            uint4 st;
            __half2* o2 = (__half2*)&st;
            #pragma unroll
            for (int k = 0; k < 4; k++) o2[k] = __hmul2(a2[k], b2h[k]);
            *((uint4*)(smc + XSOFF(buf)) + myrow * 5 + q) = st;
        }
        CP_WAIT0();
        __syncthreads();

        if (cch + 1 < NCHK) {
            if (tid < HP) {
                u32 dst = smu + WSOFF(buf ^ 1) + tid * (XH * 2);
                const char* src = wsrc + (cch + 1) * 64;
                CP16(dst, src); CP16(dst + 16, src + 16);
                CP16(dst + 32, src + 32); CP16(dst + 48, src + 48);
            }
            CP_COMMIT();
            xi = __ldg(gi16 + (cch + 1) * 4);
            xj = __ldg(gj16 + (cch + 1) * 4);
        }

        // ---- mma on buf: 2 x k16 steps
        const u32 xb = smu + XSOFF(buf);
        const u32 wb = smu + WSOFF(buf);
        #pragma unroll
        for (int s = 0; s < 2; s++) {
            u32 a[2][4];
            #pragma unroll
            for (int ma = 0; ma < 2; ma++) {
                u32 ad = xb + ((mBlk + ma * 16 + aRow) * XH + s * 16 + aK) * 2;
                LDSM4(a[ma][0], a[ma][1], a[ma][2], a[ma][3], ad);
            }
            #pragma unroll
            for (int ng = 0; ng < 2; ng++) {
                u32 ad = wb + ((nBlk + ng * 16 + bRow) * XH + s * 16 + bK) * 2;
                u32 b0, b1, b2v, b3;
                LDSM4(b0, b1, b2v, b3, ad);
                MMA_F16(c[0][2*ng],     a[0], b0, b1);
                MMA_F16(c[1][2*ng],     a[1], b0, b1);
                MMA_F16(c[0][2*ng + 1], a[0], b2v, b3);
                MMA_F16(c[1][2*ng + 1], a[1], b2v, b3);
            }
            {   // last 8 cols
                u32 ad = wb + (b2r * XH + s * 16 + b2k) * 2;
                u32 b0, b1;
                LDSM2(b0, b1, ad);
                MMA_F16(c[0][4], a[0], b0, b1);
                MMA_F16(c[1][4], a[1], b0, b1);
            }
        }
    }

    // ---- epilogue: relu + dot W2, reduce over tig, combine 4 n-blocks
    float part[2][2] = {{0.f, 0.f}, {0.f, 0.f}};
    #pragma unroll
    for (int ma = 0; ma < 2; ma++)
        #pragma unroll
        for (int na = 0; na < 5; na++) {
            int col = nBlk + na * 8 + 2 * tig;
            float w0 = w2s[col], w1 = w2s[col + 1];
            float v0 = fmaxf(c[ma][na][0], 0.f), v1 = fmaxf(c[ma][na][1], 0.f);
            float v2 = fmaxf(c[ma][na][2], 0.f), v3 = fmaxf(c[ma][na][3], 0.f);
            part[ma][0] += v0 * w0 + v1 * w1;
            part[ma][1] += v2 * w0 + v3 * w1;
        }
    #pragma unroll
    for (int ma = 0; ma < 2; ma++)
        #pragma unroll
        for (int rr = 0; rr < 2; rr++) {
            float v = part[ma][rr];
            v += __shfl_xor_sync(0xffffffffu, v, 1);
            v += __shfl_xor_sync(0xffffffffu, v, 2);
            part[ma][rr] = v;
        }
    if (tig == 0) {
        int nb = wi >> 1;
        #pragma unroll
        for (int ma = 0; ma < 2; ma++)
            #pragma unroll
            for (int rr = 0; rr < 2; rr++) {
                int row = mBlk + ma * 16 + grp + 8 * rr;
                sred[row * 4 + nb] = part[ma][rr];
            }
    }
    __syncthreads();
    if (tid < TP) {
        int p = pb + tid;
        if (p < P) {
            float s = sred[tid * 4] + sred[tid * 4 + 1] +
                      sred[tid * 4 + 2] + sred[tid * 4 + 3];
            d_scores[p] = s + __ldg(b2) + ms[s_si[tid]] + ms[s_sj[tid]];
        }
    }
}

// ---------------------------------------------------------------------------
// Ragged softmax (+epsilon logit 0), one warp per mention
// ---------------------------------------------------------------------------
__global__ void softmax_k(float* __restrict__ out, int M) {
    int warp = (blockIdx.x * blockDim.x + threadIdx.x) >> 5;
    int lane = threadIdx.x & 31;
    if (warp >= M) return;
    int s0 = d_starts[warp], s1 = d_starts[warp + 1];
    int n = s1 - s0;

    float mx = 0.0f;
    for (int i = lane; i < n; i += 32) mx = fmaxf(mx, d_scores[s0 + i]);
    #pragma unroll
    for (int off = 16; off; off >>= 1) mx = fmaxf(mx, __shfl_xor_sync(0xffffffffu, mx, off));

    float sum = 0.0f;
    for (int i = lane; i < n; i += 32) sum += expf(d_scores[s0 + i] - mx);
    #pragma unroll
    for (int off = 16; off; off >>= 1) sum += __shfl_xor_sync(0xffffffffu, sum, off);

    float eps = expf(-mx);
    float inv = 1.0f / (sum + eps);
    float* row = out + (warp + 1) * 161;
    for (int i = lane; i < n; i += 32) row[i] = expf(d_scores[s0 + i] - mx) * inv;
    if (lane == 0) row[n] = eps * inv;
}

// ---------------------------------------------------------------------------
extern "C" void kernel_launch(void* const* d_in, const int* in_sizes, int n_in,
                              void* d_out, int out_size) {
    const float* g_i   = (const float*)d_in[0];
    const float* msc   = (const float*)d_in[1];
    const float* de    = (const float*)d_in[2];
    const float* ge    = (const float*)d_in[3];
    const float* se    = (const float*)d_in[4];
    const float* W1    = (const float*)d_in[5];
    const float* b1    = (const float*)d_in[6];
    const float* W2    = (const float*)d_in[7];
    const float* b2    = (const float*)d_in[8];
    const int*   mids  = (const int*)d_in[9];
    const int*   aids  = (const int*)d_in[10];
    const int*   dists = (const int*)d_in[11];
    const int*   gens  = (const int*)d_in[12];
    const int*   spks  = (const int*)d_in[13];

    int M = in_sizes[1];
    int P = in_sizes[9];
    float* out = (float*)d_out;

    int nG16  = (M * 640 + 255) / 256;
    int nAB   = 2 * ((M + 7) / 8);
    int fillB = (out_size + 255) / 256;

    cudaFuncSetAttribute(pair_k, cudaFuncAttributeMaxDynamicSharedMemorySize, SM_TOT);

    prep_k<<<402 + nG16 + nAB + fillB, 256>>>(out, out_size, de, ge, se, W1, b1,
                                              g_i, mids, P, M, nG16, nAB);
    pair_k<<<(P + TP - 1) / TP, NT, SM_TOT>>>(W2, b2, msc,
                                              mids, aids, dists, gens, spks, P);
    softmax_k<<<(M + 7) / 8, 256>>>(out, M);
}

// round 12
// speedup vs baseline: 1.1982x; 1.1048x over previous
#include <cuda_runtime.h>
#include <cuda_fp16.h>

typedef unsigned int u32;
typedef unsigned long long ull;

#define GDIM 620
#define HH   150
#define HP   160
#define TP   64       // pairs per block (M tile)
#define NCHK 20       // 640/32
#define NT   256      // 8 warps: 2 m-blocks x 4 n-blocks

#define MMAX 1024
#define PMAX 50176

#define XH   40       // Xs/Ws row stride in halfs (LDSM conflict-free)
#define CST  168      // Ci row stride in floats

__device__ float  d_Apad[MMAX * HP];
__device__ float  d_Bpad[MMAX * HP];
__device__ float  d_distT[9 * HP];     // includes b1
__device__ float  d_genT[8 * HP];
__device__ float  d_spkT[3 * HP];
__device__ __half d_WtH[HP * 640];     // W1c^T fp16, [h][k], zero padded
__device__ __half d_g16[MMAX * 640];   // g fp16, row stride 640, zero padded
__device__ float  d_scores[PMAX];
__device__ int    d_starts[MMAX + 2];

// ---- f32x2 helpers for ab blocks ----
union U2 { ull u; float f[2]; };
__device__ __forceinline__ ull pack2(float x, float y) { U2 v; v.f[0]=x; v.f[1]=y; return v.u; }
__device__ __forceinline__ void unpack2(ull v, float& x, float& y) { U2 t; t.u=v; x=t.f[0]; y=t.f[1]; }
__device__ __forceinline__ void fma2(ull& d, ull a, ull b) {
#if defined(__CUDA_ARCH__) && (__CUDA_ARCH__ >= 1000)
    asm("fma.rn.f32x2 %0, %1, %2, %3;" : "=l"(d) : "l"(a), "l"(b), "l"(d));
#else
    U2 dd,aa,bb; dd.u=d; aa.u=a; bb.u=b;
    dd.f[0]=fmaf(aa.f[0],bb.f[0],dd.f[0]); dd.f[1]=fmaf(aa.f[1],bb.f[1],dd.f[1]); d=dd.u;
#endif
}

__device__ __forceinline__ u32 s2u(const void* p) {
    u32 a;
    asm("{ .reg .u64 t; cvta.to.shared.u64 t, %1; cvt.u32.u64 %0, t; }" : "=r"(a) : "l"(p));
    return a;
}

#define MMA_F16(C, A, B0, B1)                                               \
    asm volatile("mma.sync.aligned.m16n8k16.row.col.f32.f16.f16.f32 "       \
        "{%0,%1,%2,%3}, {%4,%5,%6,%7}, {%8,%9}, {%0,%1,%2,%3};"             \
        : "+f"((C)[0]), "+f"((C)[1]), "+f"((C)[2]), "+f"((C)[3])            \
        : "r"((A)[0]), "r"((A)[1]), "r"((A)[2]), "r"((A)[3]),               \
          "r"(B0), "r"(B1))

#define LDSM4(R0, R1, R2, R3, ADDR)                                         \
    asm volatile("ldmatrix.sync.aligned.m8n8.x4.shared.b16 {%0,%1,%2,%3}, [%4];" \
        : "=r"(R0), "=r"(R1), "=r"(R2), "=r"(R3) : "r"(ADDR))
#define LDSM2(R0, R1, ADDR)                                                 \
    asm volatile("ldmatrix.sync.aligned.m8n8.x2.shared.b16 {%0,%1}, [%2];"  \
        : "=r"(R0), "=r"(R1) : "r"(ADDR))

#define CP16(DST, SRC)                                                      \
    asm volatile("cp.async.ca.shared.global [%0], [%1], 16;" :: "r"(DST), "l"(SRC) : "memory")
#define CP_COMMIT() asm volatile("cp.async.commit_group;" ::: "memory")
#define CP_WAIT0()  asm volatile("cp.async.wait_group 0;"  ::: "memory")

// ---- shared layout (bytes). BIG: Ci (init) aliases Xs/Ws (mainloop)
#define SM_SI   0
#define SM_SJ   256
#define SM_DB   512
#define SM_GN   768
#define SM_SP   1024
#define SM_W2   1280
#define SM_SRED 1920                   // 64*4 floats
#define SM_BIG  2944
#define CI_BYTES (TP * CST * 4)        // 43008
#define XSOFF(b) (SM_BIG + (b) * 17920)   // Xs: 64*40*2 = 5120
#define WSOFF(b) (XSOFF(b) + 5120)        // Ws: 160*40*2 = 12800
#define SM_TOT  (SM_BIG + CI_BYTES)    // 45952 -> 3 CTAs/SM

// ---------------------------------------------------------------------------
// prep_k (fused, ab-first ordering):
//   [0, nAB)            ab blocks: A=g@W1a / B=g@W1b, 8 mentions, unroll-20 MLP
//   nAB                 phi tables (+b1 in distT)
//   nAB+1               segment starts
//   [nAB+2, +nWtH)      W1c^T -> fp16 (4 elems/thread)
//   [.., +nG16)         g -> fp16 padded (4 elems/thread, float4 loads)
//   rest                output fill (float4)
// ---------------------------------------------------------------------------
__global__ void prep_k(float* __restrict__ out, int n,
                       const float* __restrict__ de, const float* __restrict__ ge,
                       const float* __restrict__ se, const float* __restrict__ W1,
                       const float* __restrict__ b1, const float* __restrict__ g,
                       const int* __restrict__ mids, int P, int M,
                       int nAB, int nWtH, int nG16) {
    __shared__ float gs[GDIM][10];     // used only by ab blocks
    int b = blockIdx.x;
    int tid = threadIdx.x;

    if (b < nAB) {
        // ---- ab block: A = g@W1a (which=0) or B = g@W1b (which=1)
        int m0 = (b >> 1) * 8;
        int which = b & 1;

        for (int e = tid; e < 8 * GDIM; e += 256) {
            int mm = e / GDIM, d = e % GDIM;
            int m = m0 + mm;
            gs[d][mm] = (m < M) ? g[m * GDIM + d] : 0.0f;
        }
        __syncthreads();

        if (tid < HP) {
            const int h = tid;
            ull acc[4] = {0ull, 0ull, 0ull, 0ull};
            if (h < HH) {
                const float* w = W1 + (which ? GDIM * HH : 0) + h;
                #pragma unroll 1
                for (int d0 = 0; d0 < GDIM; d0 += 20) {   // 620 = 31 * 20
                    float wv[20];
                    #pragma unroll
                    for (int u = 0; u < 20; u++) wv[u] = __ldg(&w[(d0 + u) * HH]);
                    #pragma unroll
                    for (int u = 0; u < 20; u++) {
                        ull wp = pack2(wv[u], wv[u]);
                        const ull* grow = (const ull*)&gs[d0 + u][0];
                        fma2(acc[0], grow[0], wp);
                        fma2(acc[1], grow[1], wp);
                        fma2(acc[2], grow[2], wp);
                        fma2(acc[3], grow[3], wp);
                    }
                }
            }
            float* dst = which ? d_Bpad : d_Apad;
            #pragma unroll
            for (int r = 0; r < 4; r++) {
                float x, y; unpack2(acc[r], x, y);
                int m = m0 + 2 * r;
                if (m < M)     dst[m * HP + h] = x;
                if (m + 1 < M) dst[(m + 1) * HP + h] = y;
            }
        }
    } else if (b == nAB) {
        for (int e = tid; e < 20 * HP; e += blockDim.x) {
            int row = e / HP, h = e % HP;
            const float* emb; int dbase; float* dst; float acc;
            if (row < 9)       { emb = de + row * 20;        dbase = 3 * GDIM;      dst = d_distT + row * HP + h;        acc = (h < HH) ? b1[h] : 0.0f; }
            else if (row < 17) { emb = ge + (row - 9) * 20;  dbase = 3 * GDIM + 20; dst = d_genT  + (row - 9) * HP + h;  acc = 0.0f; }
            else               { emb = se + (row - 17) * 20; dbase = 3 * GDIM + 40; dst = d_spkT  + (row - 17) * HP + h; acc = 0.0f; }
            if (h < HH) {
                #pragma unroll
                for (int k = 0; k < 20; k++) acc += emb[k] * W1[(dbase + k) * HH + h];
            }
            *dst = acc;
        }
    } else if (b == nAB + 1) {
        for (int m = tid; m <= M; m += blockDim.x) {
            int lo = 0, hi = P;
            while (lo < hi) {
                int mid = (lo + hi) >> 1;
                if (mids[mid] < m) lo = mid + 1; else hi = mid;
            }
            d_starts[m] = lo;
        }
    } else if (b < nAB + 2 + nWtH) {
        // W1c^T -> fp16, 4 consecutive k per thread
        int e = ((b - nAB - 2) * 256 + tid) * 4;
        if (e < HP * 640) {
            int h = e / 640, k = e % 640;
            const float* W1c = W1 + 2 * GDIM * HH;
            __half hv[4];
            #pragma unroll
            for (int u = 0; u < 4; u++) {
                int kk = k + u;
                float v = (h < HH && kk < GDIM) ? __ldg(&W1c[kk * HH + h]) : 0.0f;
                hv[u] = __float2half(v);
            }
            *(ull*)(d_WtH + e) = *(ull*)hv;
        }
    } else if (b < nAB + 2 + nWtH + nG16) {
        // g -> fp16 padded, 4 consecutive k per thread (float4 fast path)
        int e = ((b - nAB - 2 - nWtH) * 256 + tid) * 4;
        if (e < M * 640) {
            int m = e / 640, k = e % 640;
            __half hv[4];
            if (k + 3 < GDIM) {
                float4 v = *(const float4*)(g + m * GDIM + k);
                hv[0] = __float2half(v.x); hv[1] = __float2half(v.y);
                hv[2] = __float2half(v.z); hv[3] = __float2half(v.w);
            } else {
                #pragma unroll
                for (int u = 0; u < 4; u++) {
                    int kk = k + u;
                    hv[u] = __float2half((kk < GDIM) ? g[m * GDIM + kk] : 0.0f);
                }
            }
            *(ull*)(d_g16 + e) = *(ull*)hv;
        }
    } else {
        // output fill (pad 1000.0; out[0] = 1.0)
        int e = ((b - nAB - 2 - nWtH - nG16) * 256 + tid) * 4;
        if (e + 3 < n) {
            float4 v = make_float4(1000.0f, 1000.0f, 1000.0f, 1000.0f);
            if (e == 0) v.x = 1.0f;
            *(float4*)(out + e) = v;
        } else {
            for (int u = 0; u < 4 && e + u < n; u++)
                out[e + u] = (e + u == 0) ? 1.0f : 1000.0f;
        }
    }
}

// ---------------------------------------------------------------------------
// pair_k: 64 pairs x 160 h per CTA, 8 warps = 2 m-blocks(32) x 4 n-blocks(40).
// Exact fp32 C init; fp16 m16n8k16 Hadamard GEMM; fp16 g source. 3 CTAs/SM.
// ---------------------------------------------------------------------------
__global__ __launch_bounds__(NT, 3) void pair_k(
    const float* __restrict__ W2,  const float* __restrict__ b2,
    const float* __restrict__ ms,
    const int* __restrict__ mids,  const int* __restrict__ aids,
    const int* __restrict__ dists, const int* __restrict__ gens,
    const int* __restrict__ spks,  int P)
{
    extern __shared__ char smc[];
    int*   s_si = (int*)(smc + SM_SI);
    int*   s_sj = (int*)(smc + SM_SJ);
    int*   s_db = (int*)(smc + SM_DB);
    int*   s_gn = (int*)(smc + SM_GN);
    int*   s_sp = (int*)(smc + SM_SP);
    float* w2s  = (float*)(smc + SM_W2);
    float* sred = (float*)(smc + SM_SRED);
    float* Ci   = (float*)(smc + SM_BIG);

    const u32 smu = s2u(smc);
    const int tid = threadIdx.x;
    const int pb  = blockIdx.x * TP;

    if (tid < TP) {
        int p = pb + tid;
        bool ok = p < P;
        s_si[tid] = ok ? mids[p] : 0;
        s_sj[tid] = ok ? aids[p] : 0;
        int dd = ok ? dists[p] : 0;
        s_db[tid] = (dd >= 1) + (dd >= 2) + (dd >= 3) + (dd >= 4) +
                    (dd >= 8) + (dd >= 16) + (dd >= 32) + (dd >= 64);
        s_gn[tid] = ok ? gens[p] : 0;
        s_sp[tid] = ok ? spks[p] : 0;
    }
    if (tid < HP) w2s[tid] = (tid < HH) ? W2[tid] : 0.0f;
    __syncthreads();

    // ---- stage exact init tile Ci[64][160] (fp32)
    {
        const float4* A4 = (const float4*)d_Apad;
        const float4* B4 = (const float4*)d_Bpad;
        const float4* D4 = (const float4*)d_distT;
        const float4* G4 = (const float4*)d_genT;
        const float4* S4 = (const float4*)d_spkT;
        #pragma unroll
        for (int it = 0; it < (TP * 40) / NT; it++) {
            int e = tid + NT * it;
            int row = e / 40, c4 = e % 40;
            float4 a = __ldg(&A4[s_si[row] * 40 + c4]);
            float4 b = __ldg(&B4[s_sj[row] * 40 + c4]);
            float4 d = __ldg(&D4[s_db[row] * 40 + c4]);
            float4 gg = __ldg(&G4[s_gn[row] * 40 + c4]);
            float4 s = __ldg(&S4[s_sp[row] * 40 + c4]);
            float4 v = make_float4(a.x+b.x+d.x+gg.x+s.x, a.y+b.y+d.y+gg.y+s.y,
                                   a.z+b.z+d.z+gg.z+s.z, a.w+b.w+d.w+gg.w+s.w);
            *(float4*)(Ci + row * CST + c4 * 4) = v;
        }
    }
    __syncthreads();

    const int lid = tid & 31, wi = tid >> 5;
    const int mBlk = (wi & 1) * 32, nBlk = (wi >> 1) * 40;
    const int tig = lid & 3, grp = lid >> 2;

    // ---- load C fragments from Ci (2 m-atoms x 5 n-atoms)
    float c[2][5][4];
    #pragma unroll
    for (int ma = 0; ma < 2; ma++) {
        int r = mBlk + ma * 16 + grp;
        #pragma unroll
        for (int na = 0; na < 5; na++) {
            int col = nBlk + na * 8 + 2 * tig;
            float2 lo = *(const float2*)(Ci + r * CST + col);
            float2 hi = *(const float2*)(Ci + (r + 8) * CST + col);
            c[ma][na][0] = lo.x; c[ma][na][1] = lo.y;
            c[ma][na][2] = hi.x; c[ma][na][3] = hi.y;
        }
    }

    // ---- pipeline setup
    const int myrow = tid >> 2, q = tid & 3;          // row 0..63, quarter 0..3
    const uint4* gi16 = (const uint4*)(d_g16 + s_si[myrow] * 640) + q;
    const uint4* gj16 = (const uint4*)(d_g16 + s_sj[myrow] * 640) + q;
    const char*  wsrc = (const char*)d_WtH + tid * 1280;   // row tid (if <160)

    // ldmatrix lane address components
    const int aRow = ((lid >> 3) & 1) * 8 + (lid & 7);
    const int aK   = (lid >> 4) * 8;
    const int bRow = (lid >> 4) * 8 + (lid & 7);
    const int bK   = ((lid >> 3) & 1) * 8;
    const int b2r  = nBlk + 32 + (lid & 7);
    const int b2k  = ((lid >> 3) & 1) * 8;

    uint4 xi, xj;
    xi = __ldg(gi16);
    xj = __ldg(gj16);
    __syncthreads();   // Ci fragment reads done; BIG region reusable

    if (tid < HP) {    // W chunk 0
        u32 dst = smu + WSOFF(0) + tid * (XH * 2);
        CP16(dst, wsrc); CP16(dst + 16, wsrc + 16);
        CP16(dst + 32, wsrc + 32); CP16(dst + 48, wsrc + 48);
    }
    CP_COMMIT();

    for (int cch = 0; cch < NCHK; cch++) {
        const int buf = cch & 1;
        {
            const __half2* a2 = (const __half2*)&xi;
            const __half2* b2h = (const __half2*)&xj;
            uint4 st;
            __half2* o2 = (__half2*)&st;
            #pragma unroll
            for (int k = 0; k < 4; k++) o2[k] = __hmul2(a2[k], b2h[k]);
            *((uint4*)(smc + XSOFF(buf)) + myrow * 5 + q) = st;
        }
        CP_WAIT0();
        __syncthreads();

        if (cch + 1 < NCHK) {
            if (tid < HP) {
                u32 dst = smu + WSOFF(buf ^ 1) + tid * (XH * 2);
                const char* src = wsrc + (cch + 1) * 64;
                CP16(dst, src); CP16(dst + 16, src + 16);
                CP16(dst + 32, src + 32); CP16(dst + 48, src + 48);
            }
            CP_COMMIT();
            xi = __ldg(gi16 + (cch + 1) * 4);
            xj = __ldg(gj16 + (cch + 1) * 4);
        }

        const u32 xb = smu + XSOFF(buf);
        const u32 wb = smu + WSOFF(buf);
        #pragma unroll
        for (int s = 0; s < 2; s++) {
            u32 a[2][4];
            #pragma unroll
            for (int ma = 0; ma < 2; ma++) {
                u32 ad = xb + ((mBlk + ma * 16 + aRow) * XH + s * 16 + aK) * 2;
                LDSM4(a[ma][0], a[ma][1], a[ma][2], a[ma][3], ad);
            }
            #pragma unroll
            for (int ng = 0; ng < 2; ng++) {
                u32 ad = wb + ((nBlk + ng * 16 + bRow) * XH + s * 16 + bK) * 2;
                u32 b0, b1, b2v, b3;
                LDSM4(b0, b1, b2v, b3, ad);
                MMA_F16(c[0][2*ng],     a[0], b0, b1);
                MMA_F16(c[1][2*ng],     a[1], b0, b1);
                MMA_F16(c[0][2*ng + 1], a[0], b2v, b3);
                MMA_F16(c[1][2*ng + 1], a[1], b2v, b3);
            }
            {
                u32 ad = wb + (b2r * XH + s * 16 + b2k) * 2;
                u32 b0, b1;
                LDSM2(b0, b1, ad);
                MMA_F16(c[0][4], a[0], b0, b1);
                MMA_F16(c[1][4], a[1], b0, b1);
            }
        }
    }

    // ---- epilogue: relu + dot W2, reduce over tig, combine 4 n-blocks
    float part[2][2] = {{0.f, 0.f}, {0.f, 0.f}};
    #pragma unroll
    for (int ma = 0; ma < 2; ma++)
        #pragma unroll
        for (int na = 0; na < 5; na++) {
            int col = nBlk + na * 8 + 2 * tig;
            float w0 = w2s[col], w1 = w2s[col + 1];
            float v0 = fmaxf(c[ma][na][0], 0.f), v1 = fmaxf(c[ma][na][1], 0.f);
            float v2 = fmaxf(c[ma][na][2], 0.f), v3 = fmaxf(c[ma][na][3], 0.f);
            part[ma][0] += v0 * w0 + v1 * w1;
            part[ma][1] += v2 * w0 + v3 * w1;
        }
    #pragma unroll
    for (int ma = 0; ma < 2; ma++)
        #pragma unroll
        for (int rr = 0; rr < 2; rr++) {
            float v = part[ma][rr];
            v += __shfl_xor_sync(0xffffffffu, v, 1);
            v += __shfl_xor_sync(0xffffffffu, v, 2);
            part[ma][rr] = v;
        }
    if (tig == 0) {
        int nb = wi >> 1;
        #pragma unroll
        for (int ma = 0; ma < 2; ma++)
            #pragma unroll
            for (int rr = 0; rr < 2; rr++) {
                int row = mBlk + ma * 16 + grp + 8 * rr;
                sred[row * 4 + nb] = part[ma][rr];
            }
    }
    __syncthreads();
    if (tid < TP) {
        int p = pb + tid;
        if (p < P) {
            float s = sred[tid * 4] + sred[tid * 4 + 1] +
                      sred[tid * 4 + 2] + sred[tid * 4 + 3];
            d_scores[p] = s + __ldg(b2) + ms[s_si[tid]] + ms[s_sj[tid]];
        }
    }
}

// ---------------------------------------------------------------------------
// Ragged softmax (+epsilon logit 0), one warp per mention
// ---------------------------------------------------------------------------
__global__ void softmax_k(float* __restrict__ out, int M) {
    int warp = (blockIdx.x * blockDim.x + threadIdx.x) >> 5;
    int lane = threadIdx.x & 31;
    if (warp >= M) return;
    int s0 = d_starts[warp], s1 = d_starts[warp + 1];
    int n = s1 - s0;

    float mx = 0.0f;
    for (int i = lane; i < n; i += 32) mx = fmaxf(mx, d_scores[s0 + i]);
    #pragma unroll
    for (int off = 16; off; off >>= 1) mx = fmaxf(mx, __shfl_xor_sync(0xffffffffu, mx, off));

    float sum = 0.0f;
    for (int i = lane; i < n; i += 32) sum += expf(d_scores[s0 + i] - mx);
    #pragma unroll
    for (int off = 16; off; off >>= 1) sum += __shfl_xor_sync(0xffffffffu, sum, off);

    float eps = expf(-mx);
    float inv = 1.0f / (sum + eps);
    float* row = out + (warp + 1) * 161;
    for (int i = lane; i < n; i += 32) row[i] = expf(d_scores[s0 + i] - mx) * inv;
    if (lane == 0) row[n] = eps * inv;
}

// ---------------------------------------------------------------------------
extern "C" void kernel_launch(void* const* d_in, const int* in_sizes, int n_in,
                              void* d_out, int out_size) {
    const float* g_i   = (const float*)d_in[0];
    const float* msc   = (const float*)d_in[1];
    const float* de    = (const float*)d_in[2];
    const float* ge    = (const float*)d_in[3];
    const float* se    = (const float*)d_in[4];
    const float* W1    = (const float*)d_in[5];
    const float* b1    = (const float*)d_in[6];
    const float* W2    = (const float*)d_in[7];
    const float* b2    = (const float*)d_in[8];
    const int*   mids  = (const int*)d_in[9];
    const int*   aids  = (const int*)d_in[10];
    const int*   dists = (const int*)d_in[11];
    const int*   gens  = (const int*)d_in[12];
    const int*   spks  = (const int*)d_in[13];

    int M = in_sizes[1];
    int P = in_sizes[9];
    float* out = (float*)d_out;

    int nAB   = 2 * ((M + 7) / 8);
    int nWtH  = (HP * 640 / 4 + 255) / 256;
    int nG16  = (M * 640 / 4 + 255) / 256;
    int fillB = ((out_size + 3) / 4 + 255) / 256;

    cudaFuncSetAttribute(pair_k, cudaFuncAttributeMaxDynamicSharedMemorySize, SM_TOT);

    prep_k<<<nAB + 2 + nWtH + nG16 + fillB, 256>>>(out, out_size, de, ge, se,
                                                   W1, b1, g_i, mids, P, M,
                                                   nAB, nWtH, nG16);
    pair_k<<<(P + TP - 1) / TP, NT, SM_TOT>>>(W2, b2, msc,
                                              mids, aids, dists, gens, spks, P);
    softmax_k<<<(M + 7) / 8, 256>>>(out, M);
}

// round 13
// speedup vs baseline: 1.2126x; 1.0120x over previous
#include <cuda_runtime.h>
#include <cuda_fp16.h>

typedef unsigned int u32;
typedef unsigned long long ull;

#define GDIM 620
#define HH   150
#define HP   160
#define TP   64       // pairs per block (M tile)
#define NCHK 20       // 640/32
#define NT   256      // 8 warps: 2 m-blocks x 4 n-blocks

#define MMAX 1024
#define PMAX 50176

#define XH   40       // Xs/Ws row stride in halfs (LDSM conflict-free)
#define CST  168      // Ci row stride in floats

__device__ float  d_Apad[MMAX * HP];
__device__ float  d_Bpad[MMAX * HP];
__device__ float  d_distT[9 * HP];     // includes b1
__device__ float  d_genT[8 * HP];
__device__ float  d_spkT[3 * HP];
__device__ __half d_WtH[480 * 640];    // [0:160) W1c^T, [160:320) W1a^T, [320:480) W1b^T
__device__ __half d_g16[MMAX * 640];   // g fp16, row stride 640, zero padded
__device__ float  d_scores[PMAX];
__device__ int    d_starts[MMAX + 2];

__device__ __forceinline__ u32 s2u(const void* p) {
    u32 a;
    asm("{ .reg .u64 t; cvta.to.shared.u64 t, %1; cvt.u32.u64 %0, t; }" : "=r"(a) : "l"(p));
    return a;
}

#define MMA_F16(C, A, B0, B1)                                               \
    asm volatile("mma.sync.aligned.m16n8k16.row.col.f32.f16.f16.f32 "       \
        "{%0,%1,%2,%3}, {%4,%5,%6,%7}, {%8,%9}, {%0,%1,%2,%3};"             \
        : "+f"((C)[0]), "+f"((C)[1]), "+f"((C)[2]), "+f"((C)[3])            \
        : "r"((A)[0]), "r"((A)[1]), "r"((A)[2]), "r"((A)[3]),               \
          "r"(B0), "r"(B1))

#define LDSM4(R0, R1, R2, R3, ADDR)                                         \
    asm volatile("ldmatrix.sync.aligned.m8n8.x4.shared.b16 {%0,%1,%2,%3}, [%4];" \
        : "=r"(R0), "=r"(R1), "=r"(R2), "=r"(R3) : "r"(ADDR))
#define LDSM2(R0, R1, ADDR)                                                 \
    asm volatile("ldmatrix.sync.aligned.m8n8.x2.shared.b16 {%0,%1}, [%2];"  \
        : "=r"(R0), "=r"(R1) : "r"(ADDR))

#define CP16(DST, SRC)                                                      \
    asm volatile("cp.async.ca.shared.global [%0], [%1], 16;" :: "r"(DST), "l"(SRC) : "memory")
#define CP_COMMIT() asm volatile("cp.async.commit_group;" ::: "memory")
#define CP_WAIT0()  asm volatile("cp.async.wait_group 0;"  ::: "memory")

// ---- pair_k shared layout (bytes). BIG: Ci (init) aliases Xs/Ws (mainloop)
#define SM_SI   0
#define SM_SJ   256
#define SM_DB   512
#define SM_GN   768
#define SM_SP   1024
#define SM_W2   1280
#define SM_SRED 1920
#define SM_BIG  2944
#define CI_BYTES (TP * CST * 4)        // 43008
#define XSOFF(b) (SM_BIG + (b) * 17920)
#define WSOFF(b) (XSOFF(b) + 5120)
#define SM_TOT  (SM_BIG + CI_BYTES)    // 45952 -> 3 CTAs/SM

// ---- abm_k shared layout: pure double buffer
#define A_XS(b) ((b) * 17920)
#define A_WS(b) (A_XS(b) + 5120)
#define ABM_TOT (2 * 17920)            // 35840

// ---------------------------------------------------------------------------
// prep_k: [0,nWtH) WtH fp16 (3 sections), [nWtH,+nG16) g16, then tables,
// starts, output fill. All independent.
// ---------------------------------------------------------------------------
__global__ void prep_k(float* __restrict__ out, int n,
                       const float* __restrict__ de, const float* __restrict__ ge,
                       const float* __restrict__ se, const float* __restrict__ W1,
                       const float* __restrict__ b1, const float* __restrict__ g,
                       const int* __restrict__ mids, int P, int M,
                       int nWtH, int nG16) {
    int b = blockIdx.x;
    int tid = threadIdx.x;

    if (b < nWtH) {
        // W1 -> fp16 transposed sections, 4 consecutive k per thread
        int e = (b * 256 + tid) * 4;
        if (e < 480 * 640) {
            int r = e / 640, k = e % 640;
            int sec = r / 160, h = r % 160;
            int base = (sec == 0) ? 2 * GDIM : ((sec == 1) ? 0 : GDIM);
            __half hv[4];
            #pragma unroll
            for (int u = 0; u < 4; u++) {
                int kk = k + u;
                float v = (h < HH && kk < GDIM) ? __ldg(&W1[(base + kk) * HH + h]) : 0.0f;
                hv[u] = __float2half(v);
            }
            *(ull*)(d_WtH + e) = *(ull*)hv;
        }
    } else if (b < nWtH + nG16) {
        int e = ((b - nWtH) * 256 + tid) * 4;
        if (e < M * 640) {
            int m = e / 640, k = e % 640;
            __half hv[4];
            if (k + 3 < GDIM) {
                float4 v = *(const float4*)(g + m * GDIM + k);
                hv[0] = __float2half(v.x); hv[1] = __float2half(v.y);
                hv[2] = __float2half(v.z); hv[3] = __float2half(v.w);
            } else {
                #pragma unroll
                for (int u = 0; u < 4; u++) {
                    int kk = k + u;
                    hv[u] = __float2half((kk < GDIM) ? g[m * GDIM + kk] : 0.0f);
                }
            }
            *(ull*)(d_g16 + e) = *(ull*)hv;
        }
    } else if (b == nWtH + nG16) {
        for (int e = tid; e < 20 * HP; e += blockDim.x) {
            int row = e / HP, h = e % HP;
            const float* emb; int dbase; float* dst; float acc;
            if (row < 9)       { emb = de + row * 20;        dbase = 3 * GDIM;      dst = d_distT + row * HP + h;        acc = (h < HH) ? b1[h] : 0.0f; }
            else if (row < 17) { emb = ge + (row - 9) * 20;  dbase = 3 * GDIM + 20; dst = d_genT  + (row - 9) * HP + h;  acc = 0.0f; }
            else               { emb = se + (row - 17) * 20; dbase = 3 * GDIM + 40; dst = d_spkT  + (row - 17) * HP + h; acc = 0.0f; }
            if (h < HH) {
                #pragma unroll
                for (int k = 0; k < 20; k++) acc += emb[k] * W1[(dbase + k) * HH + h];
            }
            *dst = acc;
        }
    } else if (b == nWtH + nG16 + 1) {
        for (int m = tid; m <= M; m += blockDim.x) {
            int lo = 0, hi = P;
            while (lo < hi) {
                int mid = (lo + hi) >> 1;
                if (mids[mid] < m) lo = mid + 1; else hi = mid;
            }
            d_starts[m] = lo;
        }
    } else {
        int e = ((b - nWtH - nG16 - 2) * 256 + tid) * 4;
        if (e + 3 < n) {
            float4 v = make_float4(1000.0f, 1000.0f, 1000.0f, 1000.0f);
            if (e == 0) v.x = 1.0f;
            *(float4*)(out + e) = v;
        } else {
            for (int u = 0; u < 4 && e + u < n; u++)
                out[e + u] = (e + u == 0) ? 1.0f : 1000.0f;
        }
    }
}

// ---------------------------------------------------------------------------
// abm_k: A/B precompute as fp16 tensor GEMM. D[64,160] = g16[tile] @ WtAB^T.
// grid (M/64, 2): y=0 -> Apad (W1a), y=1 -> Bpad (W1b). Pure cp.async fills.
// ---------------------------------------------------------------------------
__global__ __launch_bounds__(NT) void abm_k(int M) {
    extern __shared__ char smc[];
    const u32 smu = s2u(smc);
    const int tid = threadIdx.x;
    const int m0 = blockIdx.x * 64;
    const int which = blockIdx.y;

    const int lid = tid & 31, wi = tid >> 5;
    const int mBlk = (wi & 1) * 32, nBlk = (wi >> 1) * 40;
    const int tig = lid & 3, grp = lid >> 2;

    // fill pointers
    const int myrow = tid >> 2, q = tid & 3;
    const char* g_src = (const char*)(d_g16 + (m0 + myrow) * 640) + q * 16;
    const char* w_src = (const char*)(d_WtH + (160 + which * 160 + tid) * 640);
    const u32 x_dst0 = smu + (myrow * XH + q * 8) * 2;
    const u32 w_dst0 = smu + A_WS(0) - A_XS(0) * 0 + tid * (XH * 2); // Ws base + row
    // (A_WS(0) already includes Xs size offset)

    // ldmatrix lane address components
    const int aRow = ((lid >> 3) & 1) * 8 + (lid & 7);
    const int aK   = (lid >> 4) * 8;
    const int bRow = (lid >> 4) * 8 + (lid & 7);
    const int bK   = ((lid >> 3) & 1) * 8;
    const int b2r  = nBlk + 32 + (lid & 7);
    const int b2k  = ((lid >> 3) & 1) * 8;

    float c[2][5][4];
    #pragma unroll
    for (int ma = 0; ma < 2; ma++)
        #pragma unroll
        for (int na = 0; na < 5; na++)
            #pragma unroll
            for (int r = 0; r < 4; r++) c[ma][na][r] = 0.0f;

    // chunk 0 fills
    CP16(x_dst0 + A_XS(0), g_src);
    if (tid < HP) {
        u32 dst = smu + A_WS(0) + tid * (XH * 2);
        CP16(dst, w_src); CP16(dst + 16, w_src + 16);
        CP16(dst + 32, w_src + 32); CP16(dst + 48, w_src + 48);
    }
    CP_COMMIT();

    for (int cch = 0; cch < NCHK; cch++) {
        const int buf = cch & 1;
        CP_WAIT0();
        __syncthreads();

        if (cch + 1 < NCHK) {
            const int nb = buf ^ 1;
            CP16(x_dst0 + A_XS(nb), g_src + (cch + 1) * 64);
            if (tid < HP) {
                u32 dst = smu + A_WS(nb) + tid * (XH * 2);
                const char* src = w_src + (cch + 1) * 64;
                CP16(dst, src); CP16(dst + 16, src + 16);
                CP16(dst + 32, src + 32); CP16(dst + 48, src + 48);
            }
        }
        CP_COMMIT();

        const u32 xb = smu + A_XS(buf);
        const u32 wb = smu + A_WS(buf);
        #pragma unroll
        for (int s = 0; s < 2; s++) {
            u32 a[2][4];
            #pragma unroll
            for (int ma = 0; ma < 2; ma++) {
                u32 ad = xb + ((mBlk + ma * 16 + aRow) * XH + s * 16 + aK) * 2;
                LDSM4(a[ma][0], a[ma][1], a[ma][2], a[ma][3], ad);
            }
            #pragma unroll
            for (int ng = 0; ng < 2; ng++) {
                u32 ad = wb + ((nBlk + ng * 16 + bRow) * XH + s * 16 + bK) * 2;
                u32 b0, b1, b2v, b3;
                LDSM4(b0, b1, b2v, b3, ad);
                MMA_F16(c[0][2*ng],     a[0], b0, b1);
                MMA_F16(c[1][2*ng],     a[1], b0, b1);
                MMA_F16(c[0][2*ng + 1], a[0], b2v, b3);
                MMA_F16(c[1][2*ng + 1], a[1], b2v, b3);
            }
            {
                u32 ad = wb + (b2r * XH + s * 16 + b2k) * 2;
                u32 b0, b1;
                LDSM2(b0, b1, ad);
                MMA_F16(c[0][4], a[0], b0, b1);
                MMA_F16(c[1][4], a[1], b0, b1);
            }
        }
    }

    // store D
    float* dst = which ? d_Bpad : d_Apad;
    #pragma unroll
    for (int ma = 0; ma < 2; ma++) {
        int r = m0 + mBlk + ma * 16 + grp;
        #pragma unroll
        for (int na = 0; na < 5; na++) {
            int col = nBlk + na * 8 + 2 * tig;
            if (r < M)     *(float2*)&dst[r * HP + col]       = make_float2(c[ma][na][0], c[ma][na][1]);
            if (r + 8 < M) *(float2*)&dst[(r + 8) * HP + col] = make_float2(c[ma][na][2], c[ma][na][3]);
        }
    }
}

// ---------------------------------------------------------------------------
// pair_k: unchanged from R12 best (64x160, fp16 mma, X reg-prefetch + cp.async W)
// ---------------------------------------------------------------------------
__global__ __launch_bounds__(NT, 3) void pair_k(
    const float* __restrict__ W2,  const float* __restrict__ b2,
    const float* __restrict__ ms,
    const int* __restrict__ mids,  const int* __restrict__ aids,
    const int* __restrict__ dists, const int* __restrict__ gens,
    const int* __restrict__ spks,  int P)
{
    extern __shared__ char smc[];
    int*   s_si = (int*)(smc + SM_SI);
    int*   s_sj = (int*)(smc + SM_SJ);
    int*   s_db = (int*)(smc + SM_DB);
    int*   s_gn = (int*)(smc + SM_GN);
    int*   s_sp = (int*)(smc + SM_SP);
    float* w2s  = (float*)(smc + SM_W2);
    float* sred = (float*)(smc + SM_SRED);
    float* Ci   = (float*)(smc + SM_BIG);

    const u32 smu = s2u(smc);
    const int tid = threadIdx.x;
    const int pb  = blockIdx.x * TP;

    if (tid < TP) {
        int p = pb + tid;
        bool ok = p < P;
        s_si[tid] = ok ? mids[p] : 0;
        s_sj[tid] = ok ? aids[p] : 0;
        int dd = ok ? dists[p] : 0;
        s_db[tid] = (dd >= 1) + (dd >= 2) + (dd >= 3) + (dd >= 4) +
                    (dd >= 8) + (dd >= 16) + (dd >= 32) + (dd >= 64);
        s_gn[tid] = ok ? gens[p] : 0;
        s_sp[tid] = ok ? spks[p] : 0;
    }
    if (tid < HP) w2s[tid] = (tid < HH) ? W2[tid] : 0.0f;
    __syncthreads();

    {
        const float4* A4 = (const float4*)d_Apad;
        const float4* B4 = (const float4*)d_Bpad;
        const float4* D4 = (const float4*)d_distT;
        const float4* G4 = (const float4*)d_genT;
        const float4* S4 = (const float4*)d_spkT;
        #pragma unroll
        for (int it = 0; it < (TP * 40) / NT; it++) {
            int e = tid + NT * it;
            int row = e / 40, c4 = e % 40;
            float4 a = __ldg(&A4[s_si[row] * 40 + c4]);
            float4 b = __ldg(&B4[s_sj[row] * 40 + c4]);
            float4 d = __ldg(&D4[s_db[row] * 40 + c4]);
            float4 gg = __ldg(&G4[s_gn[row] * 40 + c4]);
            float4 s = __ldg(&S4[s_sp[row] * 40 + c4]);
            float4 v = make_float4(a.x+b.x+d.x+gg.x+s.x, a.y+b.y+d.y+gg.y+s.y,
                                   a.z+b.z+d.z+gg.z+s.z, a.w+b.w+d.w+gg.w+s.w);
            *(float4*)(Ci + row * CST + c4 * 4) = v;
        }
    }
    __syncthreads();

    const int lid = tid & 31, wi = tid >> 5;
    const int mBlk = (wi & 1) * 32, nBlk = (wi >> 1) * 40;
    const int tig = lid & 3, grp = lid >> 2;

    float c[2][5][4];
    #pragma unroll
    for (int ma = 0; ma < 2; ma++) {
        int r = mBlk + ma * 16 + grp;
        #pragma unroll
        for (int na = 0; na < 5; na++) {
            int col = nBlk + na * 8 + 2 * tig;
            float2 lo = *(const float2*)(Ci + r * CST + col);
            float2 hi = *(const float2*)(Ci + (r + 8) * CST + col);
            c[ma][na][0] = lo.x; c[ma][na][1] = lo.y;
            c[ma][na][2] = hi.x; c[ma][na][3] = hi.y;
        }
    }

    const int myrow = tid >> 2, q = tid & 3;
    const uint4* gi16 = (const uint4*)(d_g16 + s_si[myrow] * 640) + q;
    const uint4* gj16 = (const uint4*)(d_g16 + s_sj[myrow] * 640) + q;
    const char*  wsrc = (const char*)d_WtH + tid * 1280;

    const int aRow = ((lid >> 3) & 1) * 8 + (lid & 7);
    const int aK   = (lid >> 4) * 8;
    const int bRow = (lid >> 4) * 8 + (lid & 7);
    const int bK   = ((lid >> 3) & 1) * 8;
    const int b2r  = nBlk + 32 + (lid & 7);
    const int b2k  = ((lid >> 3) & 1) * 8;

    uint4 xi, xj;
    xi = __ldg(gi16);
    xj = __ldg(gj16);
    __syncthreads();

    if (tid < HP) {
        u32 dst = smu + WSOFF(0) + tid * (XH * 2);
        CP16(dst, wsrc); CP16(dst + 16, wsrc + 16);
        CP16(dst + 32, wsrc + 32); CP16(dst + 48, wsrc + 48);
    }
    CP_COMMIT();

    for (int cch = 0; cch < NCHK; cch++) {
        const int buf = cch & 1;
        {
            const __half2* a2 = (const __half2*)&xi;
            const __half2* b2h = (const __half2*)&xj;
            uint4 st;
            __half2* o2 = (__half2*)&st;
            #pragma unroll
            for (int k = 0; k < 4; k++) o2[k] = __hmul2(a2[k], b2h[k]);
            *((uint4*)(smc + XSOFF(buf)) + myrow * 5 + q) = st;
        }
        CP_WAIT0();
        __syncthreads();

        if (cch + 1 < NCHK) {
            if (tid < HP) {
                u32 dst = smu + WSOFF(buf ^ 1) + tid * (XH * 2);
                const char* src = wsrc + (cch + 1) * 64;
                CP16(dst, src); CP16(dst + 16, src + 16);
                CP16(dst + 32, src + 32); CP16(dst + 48, src + 48);
            }
            CP_COMMIT();
            xi = __ldg(gi16 + (cch + 1) * 4);
            xj = __ldg(gj16 + (cch + 1) * 4);
        }

        const u32 xb = smu + XSOFF(buf);
        const u32 wb = smu + WSOFF(buf);
        #pragma unroll
        for (int s = 0; s < 2; s++) {
            u32 a[2][4];
            #pragma unroll
            for (int ma = 0; ma < 2; ma++) {
                u32 ad = xb + ((mBlk + ma * 16 + aRow) * XH + s * 16 + aK) * 2;
                LDSM4(a[ma][0], a[ma][1], a[ma][2], a[ma][3], ad);
            }
            #pragma unroll
            for (int ng = 0; ng < 2; ng++) {
                u32 ad = wb + ((nBlk + ng * 16 + bRow) * XH + s * 16 + bK) * 2;
                u32 b0, b1, b2v, b3;
                LDSM4(b0, b1, b2v, b3, ad);
                MMA_F16(c[0][2*ng],     a[0], b0, b1);
                MMA_F16(c[1][2*ng],     a[1], b0, b1);
                MMA_F16(c[0][2*ng + 1], a[0], b2v, b3);
                MMA_F16(c[1][2*ng + 1], a[1], b2v, b3);
            }
            {
                u32 ad = wb + (b2r * XH + s * 16 + b2k) * 2;
                u32 b0, b1;
                LDSM2(b0, b1, ad);
                MMA_F16(c[0][4], a[0], b0, b1);
                MMA_F16(c[1][4], a[1], b0, b1);
            }
        }
    }

    float part[2][2] = {{0.f, 0.f}, {0.f, 0.f}};
    #pragma unroll
    for (int ma = 0; ma < 2; ma++)
        #pragma unroll
        for (int na = 0; na < 5; na++) {
            int col = nBlk + na * 8 + 2 * tig;
            float w0 = w2s[col], w1 = w2s[col + 1];
            float v0 = fmaxf(c[ma][na][0], 0.f), v1 = fmaxf(c[ma][na][1], 0.f);
            float v2 = fmaxf(c[ma][na][2], 0.f), v3 = fmaxf(c[ma][na][3], 0.f);
            part[ma][0] += v0 * w0 + v1 * w1;
            part[ma][1] += v2 * w0 + v3 * w1;
        }
    #pragma unroll
    for (int ma = 0; ma < 2; ma++)
        #pragma unroll
        for (int rr = 0; rr < 2; rr++) {
            float v = part[ma][rr];
            v += __shfl_xor_sync(0xffffffffu, v, 1);
            v += __shfl_xor_sync(0xffffffffu, v, 2);
            part[ma][rr] = v;
        }
    if (tig == 0) {
        int nb = wi >> 1;
        #pragma unroll
        for (int ma = 0; ma < 2; ma++)
            #pragma unroll
            for (int rr = 0; rr < 2; rr++) {
                int row = mBlk + ma * 16 + grp + 8 * rr;
                sred[row * 4 + nb] = part[ma][rr];
            }
    }
    __syncthreads();
    if (tid < TP) {
        int p = pb + tid;
        if (p < P) {
            float s = sred[tid * 4] + sred[tid * 4 + 1] +
                      sred[tid * 4 + 2] + sred[tid * 4 + 3];
            d_scores[p] = s + __ldg(b2) + ms[s_si[tid]] + ms[s_sj[tid]];
        }
    }
}

// ---------------------------------------------------------------------------
// Ragged softmax (+epsilon logit 0), one warp per mention
// ---------------------------------------------------------------------------
__global__ void softmax_k(float* __restrict__ out, int M) {
    int warp = (blockIdx.x * blockDim.x + threadIdx.x) >> 5;
    int lane = threadIdx.x & 31;
    if (warp >= M) return;
    int s0 = d_starts[warp], s1 = d_starts[warp + 1];
    int n = s1 - s0;

    float mx = 0.0f;
    for (int i = lane; i < n; i += 32) mx = fmaxf(mx, d_scores[s0 + i]);
    #pragma unroll
    for (int off = 16; off; off >>= 1) mx = fmaxf(mx, __shfl_xor_sync(0xffffffffu, mx, off));

    float sum = 0.0f;
    for (int i = lane; i < n; i += 32) sum += expf(d_scores[s0 + i] - mx);
    #pragma unroll
    for (int off = 16; off; off >>= 1) sum += __shfl_xor_sync(0xffffffffu, sum, off);

    float eps = expf(-mx);
    float inv = 1.0f / (sum + eps);
    float* row = out + (warp + 1) * 161;
    for (int i = lane; i < n; i += 32) row[i] = expf(d_scores[s0 + i] - mx) * inv;
    if (lane == 0) row[n] = eps * inv;
}

// ---------------------------------------------------------------------------
extern "C" void kernel_launch(void* const* d_in, const int* in_sizes, int n_in,
                              void* d_out, int out_size) {
    const float* g_i   = (const float*)d_in[0];
    const float* msc   = (const float*)d_in[1];
    const float* de    = (const float*)d_in[2];
    const float* ge    = (const float*)d_in[3];
    const float* se    = (const float*)d_in[4];
    const float* W1    = (const float*)d_in[5];
    const float* b1    = (const float*)d_in[6];
    const float* W2    = (const float*)d_in[7];
    const float* b2    = (const float*)d_in[8];
    const int*   mids  = (const int*)d_in[9];
    const int*   aids  = (const int*)d_in[10];
    const int*   dists = (const int*)d_in[11];
    const int*   gens  = (const int*)d_in[12];
    const int*   spks  = (const int*)d_in[13];

    int M = in_sizes[1];
    int P = in_sizes[9];
    float* out = (float*)d_out;

    int nWtH  = (480 * 640 / 4 + 255) / 256;   // 300
    int nG16  = (M * 640 / 4 + 255) / 256;
    int fillB = ((out_size + 3) / 4 + 255) / 256;

    cudaFuncSetAttribute(pair_k, cudaFuncAttributeMaxDynamicSharedMemorySize, SM_TOT);

    prep_k<<<nWtH + nG16 + 2 + fillB, 256>>>(out, out_size, de, ge, se, W1, b1,
                                             g_i, mids, P, M, nWtH, nG16);
    abm_k<<<dim3((M + 63) / 64, 2), NT, ABM_TOT>>>(M);
    pair_k<<<(P + TP - 1) / TP, NT, SM_TOT>>>(W2, b2, msc,
                                              mids, aids, dists, gens, spks, P);
    softmax_k<<<(M + 7) / 8, 256>>>(out, M);
}

// round 14
// speedup vs baseline: 1.2166x; 1.0033x over previous
#include <cuda_runtime.h>
#include <cuda_fp16.h>

typedef unsigned int u32;
typedef unsigned long long ull;

#define GDIM 620
#define HH   150
#define HP   160
#define TP   64       // pairs per block (M tile)
#define NCHK 20       // 640/32
#define NT   256      // 8 warps: 2 m-blocks x 4 n-blocks

#define MMAX 1024
#define PMAX 50176

#define XH   40       // Xs/Ws row stride in halfs (LDSM conflict-free)
#define CST  168      // Ci row stride in floats

__device__ float  d_Apad[MMAX * HP];
__device__ float  d_Bpad[MMAX * HP];
__device__ float  d_distT[9 * HP];     // includes b1
__device__ float  d_genT[8 * HP];
__device__ float  d_spkT[3 * HP];
__device__ __half d_WtH[480 * 640];    // [0:160) W1c^T, [160:320) W1a^T, [320:480) W1b^T
__device__ __half d_g16[MMAX * 640];   // g fp16, row stride 640, zero padded
__device__ float  d_scores[PMAX];
__device__ int    d_starts[MMAX + 2];

__device__ __forceinline__ u32 s2u(const void* p) {
    u32 a;
    asm("{ .reg .u64 t; cvta.to.shared.u64 t, %1; cvt.u32.u64 %0, t; }" : "=r"(a) : "l"(p));
    return a;
}

#define MMA_F16(C, A, B0, B1)                                               \
    asm volatile("mma.sync.aligned.m16n8k16.row.col.f32.f16.f16.f32 "       \
        "{%0,%1,%2,%3}, {%4,%5,%6,%7}, {%8,%9}, {%0,%1,%2,%3};"             \
        : "+f"((C)[0]), "+f"((C)[1]), "+f"((C)[2]), "+f"((C)[3])            \
        : "r"((A)[0]), "r"((A)[1]), "r"((A)[2]), "r"((A)[3]),               \
          "r"(B0), "r"(B1))

#define LDSM4(R0, R1, R2, R3, ADDR)                                         \
    asm volatile("ldmatrix.sync.aligned.m8n8.x4.shared.b16 {%0,%1,%2,%3}, [%4];" \
        : "=r"(R0), "=r"(R1), "=r"(R2), "=r"(R3) : "r"(ADDR))
#define LDSM2(R0, R1, ADDR)                                                 \
    asm volatile("ldmatrix.sync.aligned.m8n8.x2.shared.b16 {%0,%1}, [%2];"  \
        : "=r"(R0), "=r"(R1) : "r"(ADDR))

#define CP16(DST, SRC)                                                      \
    asm volatile("cp.async.ca.shared.global [%0], [%1], 16;" :: "r"(DST), "l"(SRC) : "memory")
#define CP_COMMIT() asm volatile("cp.async.commit_group;" ::: "memory")
#define CP_WAIT1()  asm volatile("cp.async.wait_group 1;"  ::: "memory")

// ---- pair_k shared layout (bytes). Ci (init) aliases X/W buffers (mainloop)
#define SM_SI   0
#define SM_SJ   256
#define SM_DB   512
#define SM_GN   768
#define SM_SP   1024
#define SM_W2   1280
#define SM_SRED 1920
#define SM_BIG  2944
#define CI_BYTES (TP * CST * 4)           // 43008
#define XSOFF(b) (SM_BIG + (b) * 5120)    // X bufs: 2 x 5120
#define WSOFF(b) (SM_BIG + 10240 + (b) * 12800)  // W ring: 3 x 12800
#define SM_TOT  (SM_BIG + 10240 + 3 * 12800)     // 51584 -> 3 CTAs/SM

// ---- abm_k shared layout: 3-stage combined ring (X 5120 + W 12800)
#define A_XS(b) ((b) * 17920)
#define A_WS(b) (A_XS(b) + 5120)
#define ABM_TOT (3 * 17920)               // 53760

// ---------------------------------------------------------------------------
// prep_k: [0,nWtH) WtH fp16 (3 sections), [nWtH,+nG16) g16, then tables,
// starts, output fill. All independent.
// ---------------------------------------------------------------------------
__global__ void prep_k(float* __restrict__ out, int n,
                       const float* __restrict__ de, const float* __restrict__ ge,
                       const float* __restrict__ se, const float* __restrict__ W1,
                       const float* __restrict__ b1, const float* __restrict__ g,
                       const int* __restrict__ mids, int P, int M,
                       int nWtH, int nG16) {
    int b = blockIdx.x;
    int tid = threadIdx.x;

    if (b < nWtH) {
        int e = (b * 256 + tid) * 4;
        if (e < 480 * 640) {
            int r = e / 640, k = e % 640;
            int sec = r / 160, h = r % 160;
            int base = (sec == 0) ? 2 * GDIM : ((sec == 1) ? 0 : GDIM);
            __half hv[4];
            #pragma unroll
            for (int u = 0; u < 4; u++) {
                int kk = k + u;
                float v = (h < HH && kk < GDIM) ? __ldg(&W1[(base + kk) * HH + h]) : 0.0f;
                hv[u] = __float2half(v);
            }
            *(ull*)(d_WtH + e) = *(ull*)hv;
        }
    } else if (b < nWtH + nG16) {
        int e = ((b - nWtH) * 256 + tid) * 4;
        if (e < M * 640) {
            int m = e / 640, k = e % 640;
            __half hv[4];
            if (k + 3 < GDIM) {
                float4 v = *(const float4*)(g + m * GDIM + k);
                hv[0] = __float2half(v.x); hv[1] = __float2half(v.y);
                hv[2] = __float2half(v.z); hv[3] = __float2half(v.w);
            } else {
                #pragma unroll
                for (int u = 0; u < 4; u++) {
                    int kk = k + u;
                    hv[u] = __float2half((kk < GDIM) ? g[m * GDIM + kk] : 0.0f);
                }
            }
            *(ull*)(d_g16 + e) = *(ull*)hv;
        }
    } else if (b == nWtH + nG16) {
        for (int e = tid; e < 20 * HP; e += blockDim.x) {
            int row = e / HP, h = e % HP;
            const float* emb; int dbase; float* dst; float acc;
            if (row < 9)       { emb = de + row * 20;        dbase = 3 * GDIM;      dst = d_distT + row * HP + h;        acc = (h < HH) ? b1[h] : 0.0f; }
            else if (row < 17) { emb = ge + (row - 9) * 20;  dbase = 3 * GDIM + 20; dst = d_genT  + (row - 9) * HP + h;  acc = 0.0f; }
            else               { emb = se + (row - 17) * 20; dbase = 3 * GDIM + 40; dst = d_spkT  + (row - 17) * HP + h; acc = 0.0f; }
            if (h < HH) {
                #pragma unroll
                for (int k = 0; k < 20; k++) acc += emb[k] * W1[(dbase + k) * HH + h];
            }
            *dst = acc;
        }
    } else if (b == nWtH + nG16 + 1) {
        for (int m = tid; m <= M; m += blockDim.x) {
            int lo = 0, hi = P;
            while (lo < hi) {
                int mid = (lo + hi) >> 1;
                if (mids[mid] < m) lo = mid + 1; else hi = mid;
            }
            d_starts[m] = lo;
        }
    } else {
        int e = ((b - nWtH - nG16 - 2) * 256 + tid) * 4;
        if (e + 3 < n) {
            float4 v = make_float4(1000.0f, 1000.0f, 1000.0f, 1000.0f);
            if (e == 0) v.x = 1.0f;
            *(float4*)(out + e) = v;
        } else {
            for (int u = 0; u < 4 && e + u < n; u++)
                out[e + u] = (e + u == 0) ? 1.0f : 1000.0f;
        }
    }
}

// ---------------------------------------------------------------------------
// abm_k: A/B precompute as fp16 tensor GEMM, 3-stage cp.async ring.
// grid (M/64, 2): y=0 -> Apad (W1a), y=1 -> Bpad (W1b).
// ---------------------------------------------------------------------------
__global__ __launch_bounds__(NT) void abm_k(int M) {
    extern __shared__ char smc[];
    const u32 smu = s2u(smc);
    const int tid = threadIdx.x;
    const int m0 = blockIdx.x * 64;
    const int which = blockIdx.y;

    const int lid = tid & 31, wi = tid >> 5;
    const int mBlk = (wi & 1) * 32, nBlk = (wi >> 1) * 40;
    const int tig = lid & 3, grp = lid >> 2;

    const int myrow = tid >> 2, q = tid & 3;
    const char* g_src = (const char*)(d_g16 + (m0 + myrow) * 640) + q * 16;
    const char* w_src = (const char*)(d_WtH + (160 + which * 160 + tid) * 640);
    const u32 x_dst = smu + (myrow * XH + q * 8) * 2;
    const u32 w_dst = smu + 5120 + tid * (XH * 2);

    const int aRow = ((lid >> 3) & 1) * 8 + (lid & 7);
    const int aK   = (lid >> 4) * 8;
    const int bRow = (lid >> 4) * 8 + (lid & 7);
    const int bK   = ((lid >> 3) & 1) * 8;
    const int b2r  = nBlk + 32 + (lid & 7);
    const int b2k  = ((lid >> 3) & 1) * 8;

    float c[2][5][4];
    #pragma unroll
    for (int ma = 0; ma < 2; ma++)
        #pragma unroll
        for (int na = 0; na < 5; na++)
            #pragma unroll
            for (int r = 0; r < 4; r++) c[ma][na][r] = 0.0f;

    // prologue: chunks 0 and 1
    #pragma unroll
    for (int pc = 0; pc < 2; pc++) {
        u32 off = pc * 17920;
        CP16(x_dst + off, g_src + pc * 64);
        if (tid < HP) {
            u32 dst = w_dst + off;
            const char* src = w_src + pc * 64;
            CP16(dst, src); CP16(dst + 16, src + 16);
            CP16(dst + 32, src + 32); CP16(dst + 48, src + 48);
        }
        CP_COMMIT();
    }

    int buf = 0;
    for (int cch = 0; cch < NCHK; cch++) {
        CP_WAIT1();
        __syncthreads();

        if (cch + 2 < NCHK) {
            int nb = buf + 2; if (nb >= 3) nb -= 3;
            u32 off = nb * 17920;
            CP16(x_dst + off, g_src + (cch + 2) * 64);
            if (tid < HP) {
                u32 dst = w_dst + off;
                const char* src = w_src + (cch + 2) * 64;
                CP16(dst, src); CP16(dst + 16, src + 16);
                CP16(dst + 32, src + 32); CP16(dst + 48, src + 48);
            }
        }
        CP_COMMIT();

        const u32 xb = smu + A_XS(buf);
        const u32 wb = smu + A_WS(buf);
        #pragma unroll
        for (int s = 0; s < 2; s++) {
            u32 a[2][4];
            #pragma unroll
            for (int ma = 0; ma < 2; ma++) {
                u32 ad = xb + ((mBlk + ma * 16 + aRow) * XH + s * 16 + aK) * 2;
                LDSM4(a[ma][0], a[ma][1], a[ma][2], a[ma][3], ad);
            }
            #pragma unroll
            for (int ng = 0; ng < 2; ng++) {
                u32 ad = wb + ((nBlk + ng * 16 + bRow) * XH + s * 16 + bK) * 2;
                u32 b0, b1, b2v, b3;
                LDSM4(b0, b1, b2v, b3, ad);
                MMA_F16(c[0][2*ng],     a[0], b0, b1);
                MMA_F16(c[1][2*ng],     a[1], b0, b1);
                MMA_F16(c[0][2*ng + 1], a[0], b2v, b3);
                MMA_F16(c[1][2*ng + 1], a[1], b2v, b3);
            }
            {
                u32 ad = wb + (b2r * XH + s * 16 + b2k) * 2;
                u32 b0, b1;
                LDSM2(b0, b1, ad);
                MMA_F16(c[0][4], a[0], b0, b1);
                MMA_F16(c[1][4], a[1], b0, b1);
            }
        }
        if (++buf == 3) buf = 0;
    }

    float* dst = which ? d_Bpad : d_Apad;
    #pragma unroll
    for (int ma = 0; ma < 2; ma++) {
        int r = m0 + mBlk + ma * 16 + grp;
        #pragma unroll
        for (int na = 0; na < 5; na++) {
            int col = nBlk + na * 8 + 2 * tig;
            if (r < M)     *(float2*)&dst[r * HP + col]       = make_float2(c[ma][na][0], c[ma][na][1]);
            if (r + 8 < M) *(float2*)&dst[(r + 8) * HP + col] = make_float2(c[ma][na][2], c[ma][na][3]);
        }
    }
}

// ---------------------------------------------------------------------------
// pair_k: 64 pairs x 160 h, 8 warps = 2m x 4n. Exact fp32 C init; fp16 mma.
// X reg-prefetch (2 bufs) + W 3-stage cp.async ring (wait_group 1). 3 CTAs/SM.
// ---------------------------------------------------------------------------
__global__ __launch_bounds__(NT, 3) void pair_k(
    const float* __restrict__ W2,  const float* __restrict__ b2,
    const float* __restrict__ ms,
    const int* __restrict__ mids,  const int* __restrict__ aids,
    const int* __restrict__ dists, const int* __restrict__ gens,
    const int* __restrict__ spks,  int P)
{
    extern __shared__ char smc[];
    int*   s_si = (int*)(smc + SM_SI);
    int*   s_sj = (int*)(smc + SM_SJ);
    int*   s_db = (int*)(smc + SM_DB);
    int*   s_gn = (int*)(smc + SM_GN);
    int*   s_sp = (int*)(smc + SM_SP);
    float* w2s  = (float*)(smc + SM_W2);
    float* sred = (float*)(smc + SM_SRED);
    float* Ci   = (float*)(smc + SM_BIG);

    const u32 smu = s2u(smc);
    const int tid = threadIdx.x;
    const int pb  = blockIdx.x * TP;

    if (tid < TP) {
        int p = pb + tid;
        bool ok = p < P;
        s_si[tid] = ok ? mids[p] : 0;
        s_sj[tid] = ok ? aids[p] : 0;
        int dd = ok ? dists[p] : 0;
        s_db[tid] = (dd >= 1) + (dd >= 2) + (dd >= 3) + (dd >= 4) +
                    (dd >= 8) + (dd >= 16) + (dd >= 32) + (dd >= 64);
        s_gn[tid] = ok ? gens[p] : 0;
        s_sp[tid] = ok ? spks[p] : 0;
    }
    if (tid < HP) w2s[tid] = (tid < HH) ? W2[tid] : 0.0f;
    __syncthreads();

    // ---- stage exact init tile Ci[64][160] (fp32)
    {
        const float4* A4 = (const float4*)d_Apad;
        const float4* B4 = (const float4*)d_Bpad;
        const float4* D4 = (const float4*)d_distT;
        const float4* G4 = (const float4*)d_genT;
        const float4* S4 = (const float4*)d_spkT;
        #pragma unroll
        for (int it = 0; it < (TP * 40) / NT; it++) {
            int e = tid + NT * it;
            int row = e / 40, c4 = e % 40;
            float4 a = __ldg(&A4[s_si[row] * 40 + c4]);
            float4 b = __ldg(&B4[s_sj[row] * 40 + c4]);
            float4 d = __ldg(&D4[s_db[row] * 40 + c4]);
            float4 gg = __ldg(&G4[s_gn[row] * 40 + c4]);
            float4 s = __ldg(&S4[s_sp[row] * 40 + c4]);
            float4 v = make_float4(a.x+b.x+d.x+gg.x+s.x, a.y+b.y+d.y+gg.y+s.y,
                                   a.z+b.z+d.z+gg.z+s.z, a.w+b.w+d.w+gg.w+s.w);
            *(float4*)(Ci + row * CST + c4 * 4) = v;
        }
    }
    __syncthreads();

    const int lid = tid & 31, wi = tid >> 5;
    const int mBlk = (wi & 1) * 32, nBlk = (wi >> 1) * 40;
    const int tig = lid & 3, grp = lid >> 2;

    // ---- load C fragments from Ci
    float c[2][5][4];
    #pragma unroll
    for (int ma = 0; ma < 2; ma++) {
        int r = mBlk + ma * 16 + grp;
        #pragma unroll
        for (int na = 0; na < 5; na++) {
            int col = nBlk + na * 8 + 2 * tig;
            float2 lo = *(const float2*)(Ci + r * CST + col);
            float2 hi = *(const float2*)(Ci + (r + 8) * CST + col);
            c[ma][na][0] = lo.x; c[ma][na][1] = lo.y;
            c[ma][na][2] = hi.x; c[ma][na][3] = hi.y;
        }
    }

    const int myrow = tid >> 2, q = tid & 3;
    const uint4* gi16 = (const uint4*)(d_g16 + s_si[myrow] * 640) + q;
    const uint4* gj16 = (const uint4*)(d_g16 + s_sj[myrow] * 640) + q;
    const char*  wsrc = (const char*)d_WtH + tid * 1280;

    const int aRow = ((lid >> 3) & 1) * 8 + (lid & 7);
    const int aK   = (lid >> 4) * 8;
    const int bRow = (lid >> 4) * 8 + (lid & 7);
    const int bK   = ((lid >> 3) & 1) * 8;
    const int b2r  = nBlk + 32 + (lid & 7);
    const int b2k  = ((lid >> 3) & 1) * 8;

    uint4 xi, xj;
    xi = __ldg(gi16);
    xj = __ldg(gj16);
    __syncthreads();   // Ci fragment reads done; X/W region reusable

    // W ring prologue: chunks 0 and 1
    #pragma unroll
    for (int pc = 0; pc < 2; pc++) {
        if (tid < HP) {
            u32 dst = smu + WSOFF(pc) + tid * (XH * 2);
            const char* src = wsrc + pc * 64;
            CP16(dst, src); CP16(dst + 16, src + 16);
            CP16(dst + 32, src + 32); CP16(dst + 48, src + 48);
        }
        CP_COMMIT();
    }

    int wbuf = 0;
    for (int cch = 0; cch < NCHK; cch++) {
        const int xbuf = cch & 1;
        // store prefetched X chunk
        {
            const __half2* a2 = (const __half2*)&xi;
            const __half2* b2h = (const __half2*)&xj;
            uint4 st;
            __half2* o2 = (__half2*)&st;
            #pragma unroll
            for (int k = 0; k < 4; k++) o2[k] = __hmul2(a2[k], b2h[k]);
            *((uint4*)(smc + XSOFF(xbuf)) + myrow * 5 + q) = st;
        }
        CP_WAIT1();          // W chunk cch landed (cch+1 may fly)
        __syncthreads();

        if (cch + 2 < NCHK) {
            int nb = wbuf + 2; if (nb >= 3) nb -= 3;
            if (tid < HP) {
                u32 dst = smu + WSOFF(nb) + tid * (XH * 2);
                const char* src = wsrc + (cch + 2) * 64;
                CP16(dst, src); CP16(dst + 16, src + 16);
                CP16(dst + 32, src + 32); CP16(dst + 48, src + 48);
            }
        }
        CP_COMMIT();
        if (cch + 1 < NCHK) {
            xi = __ldg(gi16 + (cch + 1) * 4);
            xj = __ldg(gj16 + (cch + 1) * 4);
        }

        const u32 xb = smu + XSOFF(xbuf);
        const u32 wb = smu + WSOFF(wbuf);
        #pragma unroll
        for (int s = 0; s < 2; s++) {
            u32 a[2][4];
            #pragma unroll
            for (int ma = 0; ma < 2; ma++) {
                u32 ad = xb + ((mBlk + ma * 16 + aRow) * XH + s * 16 + aK) * 2;
                LDSM4(a[ma][0], a[ma][1], a[ma][2], a[ma][3], ad);
            }
            #pragma unroll
            for (int ng = 0; ng < 2; ng++) {
                u32 ad = wb + ((nBlk + ng * 16 + bRow) * XH + s * 16 + bK) * 2;
                u32 b0, b1, b2v, b3;
                LDSM4(b0, b1, b2v, b3, ad);
                MMA_F16(c[0][2*ng],     a[0], b0, b1);
                MMA_F16(c[1][2*ng],     a[1], b0, b1);
                MMA_F16(c[0][2*ng + 1], a[0], b2v, b3);
                MMA_F16(c[1][2*ng + 1], a[1], b2v, b3);
            }
            {
                u32 ad = wb + (b2r * XH + s * 16 + b2k) * 2;
                u32 b0, b1;
                LDSM2(b0, b1, ad);
                MMA_F16(c[0][4], a[0], b0, b1);
                MMA_F16(c[1][4], a[1], b0, b1);
            }
        }
        if (++wbuf == 3) wbuf = 0;
    }

    // ---- epilogue: relu + dot W2, reduce over tig, combine 4 n-blocks
    float part[2][2] = {{0.f, 0.f}, {0.f, 0.f}};
    #pragma unroll
    for (int ma = 0; ma < 2; ma++)
        #pragma unroll
        for (int na = 0; na < 5; na++) {
            int col = nBlk + na * 8 + 2 * tig;
            float w0 = w2s[col], w1 = w2s[col + 1];
            float v0 = fmaxf(c[ma][na][0], 0.f), v1 = fmaxf(c[ma][na][1], 0.f);
            float v2 = fmaxf(c[ma][na][2], 0.f), v3 = fmaxf(c[ma][na][3], 0.f);
            part[ma][0] += v0 * w0 + v1 * w1;
            part[ma][1] += v2 * w0 + v3 * w1;
        }
    #pragma unroll
    for (int ma = 0; ma < 2; ma++)
        #pragma unroll
        for (int rr = 0; rr < 2; rr++) {
            float v = part[ma][rr];
            v += __shfl_xor_sync(0xffffffffu, v, 1);
            v += __shfl_xor_sync(0xffffffffu, v, 2);
            part[ma][rr] = v;
        }
    if (tig == 0) {
        int nb = wi >> 1;
        #pragma unroll
        for (int ma = 0; ma < 2; ma++)
            #pragma unroll
            for (int rr = 0; rr < 2; rr++) {
                int row = mBlk + ma * 16 + grp + 8 * rr;
                sred[row * 4 + nb] = part[ma][rr];
            }
    }
    __syncthreads();
    if (tid < TP) {
        int p = pb + tid;
        if (p < P) {
            float s = sred[tid * 4] + sred[tid * 4 + 1] +
                      sred[tid * 4 + 2] + sred[tid * 4 + 3];
            d_scores[p] = s + __ldg(b2) + ms[s_si[tid]] + ms[s_sj[tid]];
        }
    }
}

// ---------------------------------------------------------------------------
// Ragged softmax (+epsilon logit 0), one warp per mention
// ---------------------------------------------------------------------------
__global__ void softmax_k(float* __restrict__ out, int M) {
    int warp = (blockIdx.x * blockDim.x + threadIdx.x) >> 5;
    int lane = threadIdx.x & 31;
    if (warp >= M) return;
    int s0 = d_starts[warp], s1 = d_starts[warp + 1];
    int n = s1 - s0;

    float mx = 0.0f;
    for (int i = lane; i < n; i += 32) mx = fmaxf(mx, d_scores[s0 + i]);
    #pragma unroll
    for (int off = 16; off; off >>= 1) mx = fmaxf(mx, __shfl_xor_sync(0xffffffffu, mx, off));

    float sum = 0.0f;
    for (int i = lane; i < n; i += 32) sum += expf(d_scores[s0 + i] - mx);
    #pragma unroll
    for (int off = 16; off; off >>= 1) sum += __shfl_xor_sync(0xffffffffu, sum, off);

    float eps = expf(-mx);
    float inv = 1.0f / (sum + eps);
    float* row = out + (warp + 1) * 161;
    for (int i = lane; i < n; i += 32) row[i] = expf(d_scores[s0 + i] - mx) * inv;
    if (lane == 0) row[n] = eps * inv;
}

// ---------------------------------------------------------------------------
extern "C" void kernel_launch(void* const* d_in, const int* in_sizes, int n_in,
                              void* d_out, int out_size) {
    const float* g_i   = (const float*)d_in[0];
    const float* msc   = (const float*)d_in[1];
    const float* de    = (const float*)d_in[2];
    const float* ge    = (const float*)d_in[3];
    const float* se    = (const float*)d_in[4];
    const float* W1    = (const float*)d_in[5];
    const float* b1    = (const float*)d_in[6];
    const float* W2    = (const float*)d_in[7];
    const float* b2    = (const float*)d_in[8];
    const int*   mids  = (const int*)d_in[9];
    const int*   aids  = (const int*)d_in[10];
    const int*   dists = (const int*)d_in[11];
    const int*   gens  = (const int*)d_in[12];
    const int*   spks  = (const int*)d_in[13];

    int M = in_sizes[1];
    int P = in_sizes[9];
    float* out = (float*)d_out;

    int nWtH  = (480 * 640 / 4 + 255) / 256;   // 300
    int nG16  = (M * 640 / 4 + 255) / 256;
    int fillB = ((out_size + 3) / 4 + 255) / 256;

    cudaFuncSetAttribute(pair_k, cudaFuncAttributeMaxDynamicSharedMemorySize, SM_TOT);
    cudaFuncSetAttribute(abm_k, cudaFuncAttributeMaxDynamicSharedMemorySize, ABM_TOT);

    prep_k<<<nWtH + nG16 + 2 + fillB, 256>>>(out, out_size, de, ge, se, W1, b1,
                                             g_i, mids, P, M, nWtH, nG16);
    abm_k<<<dim3((M + 63) / 64, 2), NT, ABM_TOT>>>(M);
    pair_k<<<(P + TP - 1) / TP, NT, SM_TOT>>>(W2, b2, msc,
                                              mids, aids, dists, gens, spks, P);
    softmax_k<<<(M + 7) / 8, 256>>>(out, M);
}